// round 2
// baseline (speedup 1.0000x reference)
#include <cuda_runtime.h>
#include <cuda_bf16.h>
#include <cuda_fp8.h>
#include <stdint.h>

#define M_DIM 8192
#define K_DIM 4096
#define N_DIM 4096

// Arch-specific feature gate: tcgen05 PTX may only be emitted in sm_103a /
// sm_103f passes. In the baseline compute_103 pass these macros are all
// undefined and the mma.sync fallback body is compiled instead.
#if defined(__CUDA_ARCH__) && (__CUDA_ARCH__ >= 1000) && \
    (defined(__CUDA_ARCH_FEAT_SM103_ALL) || defined(__CUDA_ARCH_FEAT_SM100_ALL) || \
     defined(__CUDA_ARCH_SPECIFIC__) || defined(__CUDA_ARCH_FAMILY_SPECIFIC__))
#define USE_TCGEN05 1
#else
#define USE_TCGEN05 0
#endif

// ---------------- scratch (allowed: __device__ globals) ----------------
__device__ __nv_bfloat16 g_xq[(size_t)M_DIM * K_DIM];   // 64 MB
__device__ __nv_bfloat16 g_wq[(size_t)N_DIM * K_DIM];   // 32 MB

// ---------------- PTX helpers (arch-safe ones) ----------------
__device__ __forceinline__ uint32_t smem_u32(const void* p) {
    uint32_t a;
    asm("{ .reg .u64 t; cvta.to.shared.u64 t, %1; cvt.u32.u64 %0, t; }"
        : "=r"(a) : "l"(p));
    return a;
}

#if USE_TCGEN05
__device__ __forceinline__ uint32_t elect_one_pred() {
    uint32_t pred;
    asm volatile(
        "{\n\t.reg .pred p;\n\t"
        "elect.sync _|p, 0xFFFFFFFF;\n\t"
        "selp.b32 %0, 1, 0, p;\n\t}"
        : "=r"(pred));
    return pred;
}

#define MBARRIER_INIT(addr, cnt) \
    asm volatile("mbarrier.init.shared.b64 [%0], %1;" :: "r"((uint32_t)(addr)), "r"((uint32_t)(cnt)) : "memory")

#define MBARRIER_WAIT_PARITY(mbar_smem_addr, phase_parity) do { \
    uint32_t _mbar = (uint32_t)(mbar_smem_addr); \
    uint32_t _parity = (uint32_t)(phase_parity); \
    uint32_t _done; \
    asm volatile( \
        "{\n\t.reg .pred p;\n\t" \
        "mbarrier.try_wait.parity.acquire.cta.shared::cta.b64 p, [%1], %2;\n\t" \
        "selp.b32 %0, 1, 0, p;\n\t}" \
        : "=r"(_done) : "r"(_mbar), "r"(_parity) : "memory"); \
    if (!_done) { \
        asm volatile( \
            "{\n\t.reg .pred P1;\n\t" \
            "WAIT_LOOP_%=:\n\t" \
            "mbarrier.try_wait.parity.acquire.cta.shared::cta.b64 P1, [%0], %1, 0x989680;\n\t" \
            "@P1 bra.uni WAIT_DONE_%=;\n\t" \
            "bra.uni WAIT_LOOP_%=;\n\t" \
            "WAIT_DONE_%=:\n\t}" \
            :: "r"(_mbar), "r"(_parity) : "memory"); \
    } \
} while (0)

#define TCGEN05_ALLOC(smem_result_addr, nCols) \
    asm volatile("tcgen05.alloc.cta_group::1.sync.aligned.shared::cta.b32 [%0], %1;" \
        :: "r"((uint32_t)(smem_result_addr)), "r"((uint32_t)(nCols)) : "memory")

#define TCGEN05_DEALLOC(tmem_addr, nCols) \
    asm volatile("tcgen05.dealloc.cta_group::1.sync.aligned.b32 %0, %1;" \
        :: "r"(tmem_addr), "r"((uint32_t)(nCols)))

#define TCGEN05_RELINQUISH() \
    asm volatile("tcgen05.relinquish_alloc_permit.cta_group::1.sync.aligned;")

#define TCGEN05_COMMIT(mbar_smem_addr) \
    asm volatile("tcgen05.commit.cta_group::1.mbarrier::arrive::one.shared::cluster.b64 [%0];" \
        :: "r"((uint32_t)(mbar_smem_addr)) : "memory")

#define TCGEN05_WAIT_LD() \
    asm volatile("tcgen05.wait::ld.sync.aligned;" ::: "memory")

#define TCGEN05_FENCE_AFTER() \
    asm volatile("tcgen05.fence::after_thread_sync;" ::: "memory")

#define FENCE_PROXY_ASYNC_SHARED_CTA() \
    asm volatile("fence.proxy.async.shared::cta;" ::: "memory")

#define STS128(r0, r1, r2, r3, addr) \
    asm volatile("st.shared.v4.b32 [%0], {%1, %2, %3, %4};" \
        :: "r"(addr), "r"(r0), "r"(r1), "r"(r2), "r"(r3) : "memory")

#define TCGEN05_LD_32X32B_X32(r, tmem_addr) \
    asm volatile( \
        "tcgen05.ld.sync.aligned.32x32b.x32.b32 " \
        "{%0, %1, %2, %3, %4, %5, %6, %7, " \
        " %8, %9, %10, %11, %12, %13, %14, %15, " \
        " %16, %17, %18, %19, %20, %21, %22, %23, " \
        " %24, %25, %26, %27, %28, %29, %30, %31}, [%32];" \
        : "=r"((r)[0]),  "=r"((r)[1]),  "=r"((r)[2]),  "=r"((r)[3]), \
          "=r"((r)[4]),  "=r"((r)[5]),  "=r"((r)[6]),  "=r"((r)[7]), \
          "=r"((r)[8]),  "=r"((r)[9]),  "=r"((r)[10]), "=r"((r)[11]), \
          "=r"((r)[12]), "=r"((r)[13]), "=r"((r)[14]), "=r"((r)[15]), \
          "=r"((r)[16]), "=r"((r)[17]), "=r"((r)[18]), "=r"((r)[19]), \
          "=r"((r)[20]), "=r"((r)[21]), "=r"((r)[22]), "=r"((r)[23]), \
          "=r"((r)[24]), "=r"((r)[25]), "=r"((r)[26]), "=r"((r)[27]), \
          "=r"((r)[28]), "=r"((r)[29]), "=r"((r)[30]), "=r"((r)[31]) \
        : "r"(tmem_addr))

__device__ __forceinline__ uint64_t make_desc(uint32_t addr) {
    // SW128, Blackwell version=1, LBO=1 (16B), SBO=64 (1024B)
    const uint64_t base = (2ull << 61) | (1ull << 46) | (64ull << 32) | (1ull << 16);
    return base | ((uint64_t)(addr >> 4) & 0x3FFFull);
}

__device__ __forceinline__ void mma_f16_ss(uint32_t d, uint64_t a_desc, uint64_t b_desc,
                                           uint32_t idesc, uint32_t acc) {
    asm volatile(
        "{\n\t.reg .pred p;\n\t"
        "setp.ne.u32 p, %5, 0;\n\t"
        "tcgen05.mma.cta_group::1.kind::f16 [%0], %1, %2, %3, {%4, %4, %4, %4}, p;\n\t}"
        :: "r"(d), "l"(a_desc), "l"(b_desc), "r"(idesc), "r"(0u), "r"(acc)
        : "memory");
}
#endif  // USE_TCGEN05

// ---------------- dequant (fake-quant fp32 -> exact bf16) ----------------
__device__ __forceinline__ float round_e2m1(float v) {
    float a = fminf(fabsf(v), 6.0f);
    float q;
    if      (a < 0.25f) q = 0.0f;
    else if (a < 0.75f) q = 0.5f;
    else if (a < 1.25f) q = 1.0f;
    else if (a < 1.75f) q = 1.5f;
    else if (a < 2.5f)  q = 2.0f;
    else if (a < 3.5f)  q = 3.0f;
    else if (a < 5.0f)  q = 4.0f;
    else                q = 6.0f;
    return (v < 0.0f) ? -q : q;
}

__global__ void __launch_bounds__(256) dequant_kernel(const float* __restrict__ in,
                                                      __nv_bfloat16* __restrict__ out,
                                                      int ngroups) {
    int g = blockIdx.x * blockDim.x + threadIdx.x;
    if (g >= ngroups) return;

    const float4* p = reinterpret_cast<const float4*>(in) + (size_t)g * 4;
    float v[16];
    {
        float4 t0 = p[0], t1 = p[1], t2 = p[2], t3 = p[3];
        v[0]=t0.x; v[1]=t0.y; v[2]=t0.z;  v[3]=t0.w;
        v[4]=t1.x; v[5]=t1.y; v[6]=t1.z;  v[7]=t1.w;
        v[8]=t2.x; v[9]=t2.y; v[10]=t2.z; v[11]=t2.w;
        v[12]=t3.x; v[13]=t3.y; v[14]=t3.z; v[15]=t3.w;
    }

    float amax = 0.0f;
    #pragma unroll
    for (int i = 0; i < 16; i++) amax = fmaxf(amax, fabsf(v[i]));

    float sraw = __fdiv_rn(amax, 6.0f);
    __nv_fp8_e4m3 s8(sraw);
    float scale = float(s8);

    union { __nv_bfloat16 h[16]; uint4 u[2]; } pk;
    if (scale > 0.0f) {
        #pragma unroll
        for (int i = 0; i < 16; i++) {
            float q = round_e2m1(__fdiv_rn(v[i], scale));
            pk.h[i] = __float2bfloat16(q * scale);  // exact in bf16 (<=4 mantissa bits)
        }
    } else {
        #pragma unroll
        for (int i = 0; i < 16; i++) pk.h[i] = __float2bfloat16(0.0f);
    }

    uint4* q = reinterpret_cast<uint4*>(out) + (size_t)g * 2;
    q[0] = pk.u[0];
    q[1] = pk.u[1];
}

// ---------------- GEMM ----------------
#define BM 256
#define BN 256
#define BK 64
#define GEMM_THREADS 256
#define NCHUNK (K_DIM / BK)  // 64

// idesc: dtype F32, a/b BF16, N=128, M=128
#define GEMM_IDESC ((1u << 4) | (1u << 7) | (1u << 10) | ((128u / 8u) << 17) | ((128u / 16u) << 24))

#define GEMM_SMEM_BYTES (131072 + 32 + 1024)

__global__ void __launch_bounds__(GEMM_THREADS, 1)
gemm_fp4(const __nv_bfloat16* __restrict__ A,   // [M, K] row-major (xq)
         const __nv_bfloat16* __restrict__ B,   // [N, K] row-major (wq)
         const float* __restrict__ bias,        // [N]
         float* __restrict__ out)               // [M, N]
{
    extern __shared__ char smem_raw[];
    const int tid = threadIdx.x;
    const int wid = tid >> 5;
    const int lid = tid & 31;
    const int m0 = blockIdx.x * BM;
    const int n0 = blockIdx.y * BN;

#if USE_TCGEN05
    // ================= tcgen05 path (sm_103a) =================
    const uint32_t base = (smem_u32(smem_raw) + 1023u) & ~1023u;
    const uint32_t sA0 = base, sA1 = base + 32768u;
    const uint32_t sB0 = base + 65536u, sB1 = base + 98304u;
    const uint32_t tmem_ptr_addr = base + 131072u;
    const uint32_t mbar0 = base + 131080u, mbar1 = base + 131088u;

    if (wid == 0) TCGEN05_ALLOC(tmem_ptr_addr, 512);
    if (tid == 0) { MBARRIER_INIT(mbar0, 1); MBARRIER_INIT(mbar1, 1); }
    __syncthreads();

    uint32_t tmem;
    asm volatile("ld.shared.b32 %0, [%1];" : "=r"(tmem) : "r"(tmem_ptr_addr));

    uint32_t soff[8];
    const uint4* aP[8];
    const uint4* bP[8];
    {
        const __nv_bfloat16* Ag = A + (size_t)m0 * K_DIM;
        const __nv_bfloat16* Bg = B + (size_t)n0 * K_DIM;
        #pragma unroll
        for (int j = 0; j < 8; j++) {
            int idx = j * GEMM_THREADS + tid;
            int row = idx >> 3;
            int seg = idx & 7;
            uint32_t boff = (uint32_t)row * 128u + (uint32_t)seg * 16u;
            soff[j] = boff ^ ((boff >> 3) & 0x70u);   // SW128
            aP[j] = reinterpret_cast<const uint4*>(Ag + (size_t)row * K_DIM) + seg;
            bP[j] = reinterpret_cast<const uint4*>(Bg + (size_t)row * K_DIM) + seg;
        }
    }

    for (int c = 0; c < NCHUNK; c++) {
        const int b = c & 1;
        const uint32_t mb = b ? mbar1 : mbar0;
        const uint32_t sa = b ? sA1 : sA0;
        const uint32_t sb = b ? sB1 : sB0;

        if (c >= 2) MBARRIER_WAIT_PARITY(mb, ((c >> 1) - 1) & 1);

        const int koff = c * (BK / 8);
        #pragma unroll
        for (int j = 0; j < 8; j++) {
            uint4 va = aP[j][koff];
            STS128(va.x, va.y, va.z, va.w, sa + soff[j]);
        }
        #pragma unroll
        for (int j = 0; j < 8; j++) {
            uint4 vb = bP[j][koff];
            STS128(vb.x, vb.y, vb.z, vb.w, sb + soff[j]);
        }
        FENCE_PROXY_ASYNC_SHARED_CTA();
        __syncthreads();

        if (wid == 0 && elect_one_pred()) {
            uint64_t ad0 = make_desc(sa);
            uint64_t ad1 = make_desc(sa + 16384u);
            uint64_t bd0 = make_desc(sb);
            uint64_t bd1 = make_desc(sb + 16384u);
            #pragma unroll
            for (int ks = 0; ks < 4; ks++) {
                uint32_t acc = (c > 0 || ks > 0) ? 1u : 0u;
                uint64_t kadd = (uint64_t)(ks * 2);
                mma_f16_ss(tmem + 0u,   ad0 + kadd, bd0 + kadd, GEMM_IDESC, acc);
                mma_f16_ss(tmem + 128u, ad0 + kadd, bd1 + kadd, GEMM_IDESC, acc);
                mma_f16_ss(tmem + 256u, ad1 + kadd, bd0 + kadd, GEMM_IDESC, acc);
                mma_f16_ss(tmem + 384u, ad1 + kadd, bd1 + kadd, GEMM_IDESC, acc);
            }
            TCGEN05_COMMIT(mb);
        }
    }

    MBARRIER_WAIT_PARITY(mbar0, ((NCHUNK / 2) - 1) & 1);
    MBARRIER_WAIT_PARITY(mbar1, ((NCHUNK / 2) - 1) & 1);
    TCGEN05_FENCE_AFTER();
    __syncthreads();

    {
        const int sp = wid & 3;
        const int dsel = wid >> 2;
        const uint32_t epi = base + (uint32_t)wid * 4224u;  // 32*33*4
        const int mbase = m0 + dsel * 128 + sp * 32;
        const uint32_t dbase = tmem + (uint32_t)(dsel * 256);

        for (int cc = 0; cc < BN; cc += 32) {
            uint32_t d[32];
            TCGEN05_LD_32X32B_X32(d, dbase + (uint32_t)cc);
            TCGEN05_WAIT_LD();
            #pragma unroll
            for (int j = 0; j < 32; j++) {
                float v = __uint_as_float(d[j]) + __ldg(bias + n0 + cc + j);
                asm volatile("st.shared.f32 [%0], %1;"
                             :: "r"(epi + ((uint32_t)lid * 33u + (uint32_t)j) * 4u), "f"(v) : "memory");
            }
            __syncwarp();
            #pragma unroll
            for (int r = 0; r < 32; r++) {
                float v;
                asm volatile("ld.shared.f32 %0, [%1];"
                             : "=f"(v) : "r"(epi + ((uint32_t)r * 33u + (uint32_t)lid) * 4u));
                out[(size_t)(mbase + r) * N_DIM + (size_t)(n0 + cc + lid)] = v;
            }
            __syncwarp();
        }
    }

    __syncthreads();
    if (wid == 0) {
        TCGEN05_RELINQUISH();
        TCGEN05_DEALLOC(tmem, 512);
    }

#else
    // ================= mma.sync fallback (baseline sm_103 / sm_100) =================
    // 256x256 CTA tile = 4x (128x128) sub-tiles, full K sweep per sub-tile.
    // 8 warps arranged 4(M) x 2(N): warp tile 32x64. mma.m16n8k16 bf16.
    __nv_bfloat16* fA = reinterpret_cast<__nv_bfloat16*>(smem_raw);   // [128][64]
    __nv_bfloat16* fB = fA + 128 * 64;                                 // [128][64]

    const int wr = wid >> 1;      // 0..3 -> M block of 32
    const int wc = wid & 1;       // 0..1 -> N block of 64
    const int lq = lid >> 2;      // lane/4
    const int lr = (lid & 3) * 2; // (lane%4)*2

    for (int sub = 0; sub < 4; sub++) {
        const int sm0 = m0 + (sub >> 1) * 128;
        const int sn0 = n0 + (sub & 1) * 128;

        float acc[16][4];
        #pragma unroll
        for (int i = 0; i < 16; i++)
            #pragma unroll
            for (int j = 0; j < 4; j++) acc[i][j] = 0.0f;

        for (int c = 0; c < NCHUNK; c++) {
            __syncthreads();
            // load A sub-tile 128x64 and B sub-tile 128x64 (8 uint4 per row)
            #pragma unroll
            for (int j = 0; j < 4; j++) {
                int idx = j * GEMM_THREADS + tid;
                int row = idx >> 3;
                int seg = idx & 7;
                reinterpret_cast<uint4*>(fA)[row * 8 + seg] =
                    *(reinterpret_cast<const uint4*>(A + (size_t)(sm0 + row) * K_DIM + c * BK) + seg);
                reinterpret_cast<uint4*>(fB)[row * 8 + seg] =
                    *(reinterpret_cast<const uint4*>(B + (size_t)(sn0 + row) * K_DIM + c * BK) + seg);
            }
            __syncthreads();

            #pragma unroll
            for (int kk = 0; kk < 4; kk++) {
                const int kb = kk * 16;
                uint32_t afr[2][4];
                #pragma unroll
                for (int mt = 0; mt < 2; mt++) {
                    int ar = wr * 32 + mt * 16 + lq;
                    int ac = kb + lr;
                    afr[mt][0] = *reinterpret_cast<const uint32_t*>(fA + ar * 64 + ac);
                    afr[mt][1] = *reinterpret_cast<const uint32_t*>(fA + (ar + 8) * 64 + ac);
                    afr[mt][2] = *reinterpret_cast<const uint32_t*>(fA + ar * 64 + ac + 8);
                    afr[mt][3] = *reinterpret_cast<const uint32_t*>(fA + (ar + 8) * 64 + ac + 8);
                }
                uint32_t bfr[8][2];
                #pragma unroll
                for (int nt = 0; nt < 8; nt++) {
                    int bn = wc * 64 + nt * 8 + lq;
                    int bk = kb + lr;
                    bfr[nt][0] = *reinterpret_cast<const uint32_t*>(fB + bn * 64 + bk);
                    bfr[nt][1] = *reinterpret_cast<const uint32_t*>(fB + bn * 64 + bk + 8);
                }
                #pragma unroll
                for (int mt = 0; mt < 2; mt++)
                    #pragma unroll
                    for (int nt = 0; nt < 8; nt++) {
                        float* d = acc[mt * 8 + nt];
                        asm volatile(
                            "mma.sync.aligned.m16n8k16.row.col.f32.bf16.bf16.f32 "
                            "{%0,%1,%2,%3}, {%4,%5,%6,%7}, {%8,%9}, {%0,%1,%2,%3};"
                            : "+f"(d[0]), "+f"(d[1]), "+f"(d[2]), "+f"(d[3])
                            : "r"(afr[mt][0]), "r"(afr[mt][1]), "r"(afr[mt][2]), "r"(afr[mt][3]),
                              "r"(bfr[nt][0]), "r"(bfr[nt][1]));
                    }
            }
        }

        // write out with bias
        #pragma unroll
        for (int mt = 0; mt < 2; mt++) {
            #pragma unroll
            for (int nt = 0; nt < 8; nt++) {
                const float* d = acc[mt * 8 + nt];
                int r0 = sm0 + wr * 32 + mt * 16 + lq;
                int col = sn0 + wc * 64 + nt * 8 + lr;
                float b0 = __ldg(bias + col);
                float b1 = __ldg(bias + col + 1);
                out[(size_t)r0 * N_DIM + col]            = d[0] + b0;
                out[(size_t)r0 * N_DIM + col + 1]        = d[1] + b1;
                out[(size_t)(r0 + 8) * N_DIM + col]      = d[2] + b0;
                out[(size_t)(r0 + 8) * N_DIM + col + 1]  = d[3] + b1;
            }
        }
        __syncthreads();
    }
#endif
}

// ---------------- launcher ----------------
extern "C" void kernel_launch(void* const* d_in, const int* in_sizes, int n_in,
                              void* d_out, int out_size) {
    (void)in_sizes; (void)n_in; (void)out_size;
    const float* x    = (const float*)d_in[0];   // [8192, 4096]
    const float* w    = (const float*)d_in[1];   // [4096, 4096]
    const float* bias = (const float*)d_in[2];   // [4096]
    float* out = (float*)d_out;                  // [8192, 4096]

    __nv_bfloat16 *xq = nullptr, *wq = nullptr;
    cudaGetSymbolAddress((void**)&xq, g_xq);
    cudaGetSymbolAddress((void**)&wq, g_wq);

    const int xg = M_DIM * K_DIM / 16;
    const int wg = N_DIM * K_DIM / 16;
    dequant_kernel<<<xg / 256, 256>>>(x, xq, xg);
    dequant_kernel<<<wg / 256, 256>>>(w, wq, wg);

    cudaFuncSetAttribute(gemm_fp4, cudaFuncAttributeMaxDynamicSharedMemorySize, GEMM_SMEM_BYTES);
    dim3 grid(M_DIM / BM, N_DIM / BN);  // (32, 16)
    gemm_fp4<<<grid, GEMM_THREADS, GEMM_SMEM_BYTES>>>(xq, wq, bias, out);
}

// round 3
// speedup vs baseline: 1.4648x; 1.4648x over previous
#include <cuda_runtime.h>
#include <cuda_bf16.h>
#include <cuda_fp8.h>
#include <stdint.h>

#define M_DIM 8192
#define K_DIM 4096
#define N_DIM 4096

// Arch-specific feature gate: tcgen05 PTX may only be emitted in sm_103a /
// sm_103f passes. In the baseline compute_103 pass these macros are all
// undefined and the mma.sync fallback body is compiled instead.
#if defined(__CUDA_ARCH__) && (__CUDA_ARCH__ >= 1000) && \
    (defined(__CUDA_ARCH_FEAT_SM103_ALL) || defined(__CUDA_ARCH_FEAT_SM100_ALL) || \
     defined(__CUDA_ARCH_SPECIFIC__) || defined(__CUDA_ARCH_FAMILY_SPECIFIC__))
#define USE_TCGEN05 1
#else
#define USE_TCGEN05 0
#endif

// ---------------- scratch (allowed: __device__ globals) ----------------
__device__ __nv_bfloat16 g_xq[(size_t)M_DIM * K_DIM];   // 64 MB
__device__ __nv_bfloat16 g_wq[(size_t)N_DIM * K_DIM];   // 32 MB
__device__ unsigned int g_tile_ctr;

__global__ void reset_ctr_kernel() { g_tile_ctr = 0u; }

// ---------------- PTX helpers ----------------
__device__ __forceinline__ uint32_t smem_u32(const void* p) {
    uint32_t a;
    asm("{ .reg .u64 t; cvta.to.shared.u64 t, %1; cvt.u32.u64 %0, t; }"
        : "=r"(a) : "l"(p));
    return a;
}

// cp.async is legal PTX since sm_80 -> safe in the baseline pass too.
#define CP_ASYNC16(dst, src) \
    asm volatile("cp.async.cg.shared.global [%0], [%1], 16;" \
        :: "r"((uint32_t)(dst)), "l"(src) : "memory")
#define CP_COMMIT() asm volatile("cp.async.commit_group;" ::: "memory")
#define CP_WAIT1()  asm volatile("cp.async.wait_group 1;" ::: "memory")

#if USE_TCGEN05
__device__ __forceinline__ uint32_t elect_one_pred() {
    uint32_t pred;
    asm volatile(
        "{\n\t.reg .pred p;\n\t"
        "elect.sync _|p, 0xFFFFFFFF;\n\t"
        "selp.b32 %0, 1, 0, p;\n\t}"
        : "=r"(pred));
    return pred;
}

#define MBARRIER_INIT(addr, cnt) \
    asm volatile("mbarrier.init.shared.b64 [%0], %1;" :: "r"((uint32_t)(addr)), "r"((uint32_t)(cnt)) : "memory")

#define MBARRIER_WAIT_PARITY(mbar_smem_addr, phase_parity) do { \
    uint32_t _mbar = (uint32_t)(mbar_smem_addr); \
    uint32_t _parity = (uint32_t)(phase_parity); \
    uint32_t _done; \
    asm volatile( \
        "{\n\t.reg .pred p;\n\t" \
        "mbarrier.try_wait.parity.acquire.cta.shared::cta.b64 p, [%1], %2;\n\t" \
        "selp.b32 %0, 1, 0, p;\n\t}" \
        : "=r"(_done) : "r"(_mbar), "r"(_parity) : "memory"); \
    if (!_done) { \
        asm volatile( \
            "{\n\t.reg .pred P1;\n\t" \
            "WAIT_LOOP_%=:\n\t" \
            "mbarrier.try_wait.parity.acquire.cta.shared::cta.b64 P1, [%0], %1, 0x989680;\n\t" \
            "@P1 bra.uni WAIT_DONE_%=;\n\t" \
            "bra.uni WAIT_LOOP_%=;\n\t" \
            "WAIT_DONE_%=:\n\t}" \
            :: "r"(_mbar), "r"(_parity) : "memory"); \
    } \
} while (0)

#define TCGEN05_ALLOC(smem_result_addr, nCols) \
    asm volatile("tcgen05.alloc.cta_group::1.sync.aligned.shared::cta.b32 [%0], %1;" \
        :: "r"((uint32_t)(smem_result_addr)), "r"((uint32_t)(nCols)) : "memory")

#define TCGEN05_DEALLOC(tmem_addr, nCols) \
    asm volatile("tcgen05.dealloc.cta_group::1.sync.aligned.b32 %0, %1;" \
        :: "r"(tmem_addr), "r"((uint32_t)(nCols)))

#define TCGEN05_RELINQUISH() \
    asm volatile("tcgen05.relinquish_alloc_permit.cta_group::1.sync.aligned;")

#define TCGEN05_COMMIT(mbar_smem_addr) \
    asm volatile("tcgen05.commit.cta_group::1.mbarrier::arrive::one.shared::cluster.b64 [%0];" \
        :: "r"((uint32_t)(mbar_smem_addr)) : "memory")

#define TCGEN05_WAIT_LD() \
    asm volatile("tcgen05.wait::ld.sync.aligned;" ::: "memory")

#define TCGEN05_FENCE_AFTER() \
    asm volatile("tcgen05.fence::after_thread_sync;" ::: "memory")

#define FENCE_PROXY_ASYNC_SHARED_CTA() \
    asm volatile("fence.proxy.async.shared::cta;" ::: "memory")

#define TCGEN05_LD_32X32B_X32(r, tmem_addr) \
    asm volatile( \
        "tcgen05.ld.sync.aligned.32x32b.x32.b32 " \
        "{%0, %1, %2, %3, %4, %5, %6, %7, " \
        " %8, %9, %10, %11, %12, %13, %14, %15, " \
        " %16, %17, %18, %19, %20, %21, %22, %23, " \
        " %24, %25, %26, %27, %28, %29, %30, %31}, [%32];" \
        : "=r"((r)[0]),  "=r"((r)[1]),  "=r"((r)[2]),  "=r"((r)[3]), \
          "=r"((r)[4]),  "=r"((r)[5]),  "=r"((r)[6]),  "=r"((r)[7]), \
          "=r"((r)[8]),  "=r"((r)[9]),  "=r"((r)[10]), "=r"((r)[11]), \
          "=r"((r)[12]), "=r"((r)[13]), "=r"((r)[14]), "=r"((r)[15]), \
          "=r"((r)[16]), "=r"((r)[17]), "=r"((r)[18]), "=r"((r)[19]), \
          "=r"((r)[20]), "=r"((r)[21]), "=r"((r)[22]), "=r"((r)[23]), \
          "=r"((r)[24]), "=r"((r)[25]), "=r"((r)[26]), "=r"((r)[27]), \
          "=r"((r)[28]), "=r"((r)[29]), "=r"((r)[30]), "=r"((r)[31]) \
        : "r"(tmem_addr))

__device__ __forceinline__ uint64_t make_desc(uint32_t addr) {
    // SW128, Blackwell version=1, LBO=1 (16B), SBO=64 (1024B)
    const uint64_t base = (2ull << 61) | (1ull << 46) | (64ull << 32) | (1ull << 16);
    return base | ((uint64_t)(addr >> 4) & 0x3FFFull);
}

__device__ __forceinline__ void mma_f16_ss(uint32_t d, uint64_t a_desc, uint64_t b_desc,
                                           uint32_t idesc, uint32_t acc) {
    asm volatile(
        "{\n\t.reg .pred p;\n\t"
        "setp.ne.u32 p, %5, 0;\n\t"
        "tcgen05.mma.cta_group::1.kind::f16 [%0], %1, %2, %3, {%4, %4, %4, %4}, p;\n\t}"
        :: "r"(d), "l"(a_desc), "l"(b_desc), "r"(idesc), "r"(0u), "r"(acc)
        : "memory");
}
#endif  // USE_TCGEN05

// ---------------- dequant (fake-quant fp32 -> exact bf16; proven rel_err 0.0) ----
__device__ __forceinline__ float round_e2m1(float v) {
    float a = fminf(fabsf(v), 6.0f);
    float q;
    if      (a < 0.25f) q = 0.0f;
    else if (a < 0.75f) q = 0.5f;
    else if (a < 1.25f) q = 1.0f;
    else if (a < 1.75f) q = 1.5f;
    else if (a < 2.5f)  q = 2.0f;
    else if (a < 3.5f)  q = 3.0f;
    else if (a < 5.0f)  q = 4.0f;
    else                q = 6.0f;
    return (v < 0.0f) ? -q : q;
}

__global__ void __launch_bounds__(256) dequant_kernel(const float* __restrict__ in,
                                                      __nv_bfloat16* __restrict__ out,
                                                      int ngroups) {
    int g = blockIdx.x * blockDim.x + threadIdx.x;
    if (g >= ngroups) return;

    const float4* p = reinterpret_cast<const float4*>(in) + (size_t)g * 4;
    float v[16];
    {
        float4 t0 = p[0], t1 = p[1], t2 = p[2], t3 = p[3];
        v[0]=t0.x; v[1]=t0.y; v[2]=t0.z;  v[3]=t0.w;
        v[4]=t1.x; v[5]=t1.y; v[6]=t1.z;  v[7]=t1.w;
        v[8]=t2.x; v[9]=t2.y; v[10]=t2.z; v[11]=t2.w;
        v[12]=t3.x; v[13]=t3.y; v[14]=t3.z; v[15]=t3.w;
    }

    float amax = 0.0f;
    #pragma unroll
    for (int i = 0; i < 16; i++) amax = fmaxf(amax, fabsf(v[i]));

    float sraw = __fdiv_rn(amax, 6.0f);
    __nv_fp8_e4m3 s8(sraw);
    float scale = float(s8);

    union { __nv_bfloat16 h[16]; uint4 u[2]; } pk;
    if (scale > 0.0f) {
        #pragma unroll
        for (int i = 0; i < 16; i++) {
            float q = round_e2m1(__fdiv_rn(v[i], scale));
            pk.h[i] = __float2bfloat16(q * scale);  // exact in bf16 (<=4 mantissa bits)
        }
    } else {
        #pragma unroll
        for (int i = 0; i < 16; i++) pk.h[i] = __float2bfloat16(0.0f);
    }

    uint4* q = reinterpret_cast<uint4*>(out) + (size_t)g * 2;
    q[0] = pk.u[0];
    q[1] = pk.u[1];
}

// ---------------- GEMM ----------------
#define BM 256
#define BN 256
#define BK 64
#define GEMM_THREADS 256
#define NCHUNK (K_DIM / BK)          // 64
#define NT_X (N_DIM / BN)            // 16
#define NTILES ((M_DIM / BM) * NT_X) // 512
#define NSTAGE 3
#define STAGE_BYTES 65536            // A 32KB + B 32KB per stage

// idesc: dtype F32, a/b BF16, N=128, M=128
#define GEMM_IDESC ((1u << 4) | (1u << 7) | (1u << 10) | ((128u / 8u) << 17) | ((128u / 16u) << 24))

// base(1024-align pad) + 3 stages + header (tmem_ptr, 3 mbarriers, tile slot)
#define GEMM_SMEM_BYTES (NSTAGE * STAGE_BYTES + 64 + 1024)

__device__ __forceinline__ void issue_chunk_loads(
    uint32_t stage_base, const uint4* __restrict__ aC, const uint4* __restrict__ bC,
    const uint32_t* soff, const uint32_t* g4o)
{
    #pragma unroll
    for (int j = 0; j < 8; j++)
        CP_ASYNC16(stage_base + soff[j], (const void*)(aC + g4o[j]));
    #pragma unroll
    for (int j = 0; j < 8; j++)
        CP_ASYNC16(stage_base + 32768u + soff[j], (const void*)(bC + g4o[j]));
}

__global__ void __launch_bounds__(GEMM_THREADS, 1)
gemm_fp4(const __nv_bfloat16* __restrict__ A,   // [M, K] row-major (xq)
         const __nv_bfloat16* __restrict__ B,   // [N, K] row-major (wq)
         const float* __restrict__ bias,        // [N]
         float* __restrict__ out)               // [M, N]
{
    extern __shared__ char smem_raw[];
    const int tid = threadIdx.x;
    const int wid = tid >> 5;
    const int lid = tid & 31;

#if USE_TCGEN05
    // ================= persistent tcgen05 path (sm_103a) =================
    const uint32_t base = (smem_u32(smem_raw) + 1023u) & ~1023u;
    const uint32_t header = base + NSTAGE * STAGE_BYTES;
    const uint32_t tmem_ptr_addr = header;
    const uint32_t mbar_base = header + 8u;      // 3 x 8B
    const uint32_t tile_slot = header + 32u;

    if (wid == 0) TCGEN05_ALLOC(tmem_ptr_addr, 512);
    if (tid == 0) {
        MBARRIER_INIT(mbar_base + 0u, 1);
        MBARRIER_INIT(mbar_base + 8u, 1);
        MBARRIER_INIT(mbar_base + 16u, 1);
    }
    __syncthreads();

    uint32_t tmem;
    asm volatile("ld.shared.b32 %0, [%1];" : "=r"(tmem) : "r"(tmem_ptr_addr));

    // Per-thread load slot geometry (tile = 256 rows x 128B = 2048 x 16B; 8/thread)
    uint32_t soff[8], g4o[8];
    #pragma unroll
    for (int j = 0; j < 8; j++) {
        int idx = j * GEMM_THREADS + tid;
        int row = idx >> 3;
        int seg = idx & 7;
        uint32_t boff = (uint32_t)row * 128u + (uint32_t)seg * 16u;
        soff[j] = boff ^ ((boff >> 3) & 0x70u);   // SW128
        g4o[j] = (uint32_t)row * (K_DIM / 8) + (uint32_t)seg;
    }

    // mbarrier firing counters per buffer (persist across tiles)
    uint32_t nf0 = 0, nf1 = 0, nf2 = 0;

    while (true) {
        if (tid == 0) {
            unsigned int t = atomicAdd(&g_tile_ctr, 1u);
            asm volatile("st.shared.u32 [%0], %1;" :: "r"(tile_slot), "r"(t) : "memory");
        }
        __syncthreads();
        uint32_t t;
        asm volatile("ld.shared.u32 %0, [%1];" : "=r"(t) : "r"(tile_slot));
        if (t >= NTILES) break;

        const int m0 = (int)(t / NT_X) * BM;
        const int n0 = (int)(t % NT_X) * BN;
        const uint4* Ag4 = reinterpret_cast<const uint4*>(A + (size_t)m0 * K_DIM);
        const uint4* Bg4 = reinterpret_cast<const uint4*>(B + (size_t)n0 * K_DIM);

        // prologue: chunks 0,1 -> buffers 0,1
        issue_chunk_loads(base + 0u * STAGE_BYTES, Ag4 + 0 * 8, Bg4 + 0 * 8, soff, g4o);
        CP_COMMIT();
        issue_chunk_loads(base + 1u * STAGE_BYTES, Ag4 + 1 * 8, Bg4 + 1 * 8, soff, g4o);
        CP_COMMIT();

        for (int c = 0; c < NCHUNK; c++) {
            const int s = c % 3;
            const uint32_t sa = base + (uint32_t)s * STAGE_BYTES;
            const uint32_t sb = sa + 32768u;

            CP_WAIT1();                         // chunk c data in SMEM
            FENCE_PROXY_ASYNC_SHARED_CTA();
            __syncthreads();

            if (wid == 0 && elect_one_pred()) {
                uint64_t ad0 = make_desc(sa);
                uint64_t ad1 = make_desc(sa + 16384u);
                uint64_t bd0 = make_desc(sb);
                uint64_t bd1 = make_desc(sb + 16384u);
                #pragma unroll
                for (int ks = 0; ks < 4; ks++) {
                    uint32_t acc = (c > 0 || ks > 0) ? 1u : 0u;
                    uint64_t kadd = (uint64_t)(ks * 2);
                    mma_f16_ss(tmem + 0u,   ad0 + kadd, bd0 + kadd, GEMM_IDESC, acc);
                    mma_f16_ss(tmem + 128u, ad0 + kadd, bd1 + kadd, GEMM_IDESC, acc);
                    mma_f16_ss(tmem + 256u, ad1 + kadd, bd0 + kadd, GEMM_IDESC, acc);
                    mma_f16_ss(tmem + 384u, ad1 + kadd, bd1 + kadd, GEMM_IDESC, acc);
                }
                TCGEN05_COMMIT(mbar_base + (uint32_t)s * 8u);
            }

            if (c + 2 < NCHUNK) {
                if (c >= 1) {
                    // buffer (c+2)%3 == (c-1)%3: wait until MMA of chunk c-1 done reading
                    const int ws = (c - 1) % 3;
                    uint32_t par = (ws == 0 ? nf0 : (ws == 1 ? nf1 : nf2)) & 1u;
                    MBARRIER_WAIT_PARITY(mbar_base + (uint32_t)ws * 8u, par);
                    if (ws == 0) nf0++; else if (ws == 1) nf1++; else nf2++;
                }
                const uint32_t dst = base + (uint32_t)((c + 2) % 3) * STAGE_BYTES;
                issue_chunk_loads(dst, Ag4 + (c + 2) * 8, Bg4 + (c + 2) * 8, soff, g4o);
            }
            CP_COMMIT();   // one group per iteration keeps wait_group accounting fixed
        }

        // drain: outstanding MMA firings are chunks 61(buf1), 62(buf2), 63(buf0)
        MBARRIER_WAIT_PARITY(mbar_base + 8u,  nf1 & 1u); nf1++;
        MBARRIER_WAIT_PARITY(mbar_base + 16u, nf2 & 1u); nf2++;
        MBARRIER_WAIT_PARITY(mbar_base + 0u,  nf0 & 1u); nf0++;
        TCGEN05_FENCE_AFTER();
        __syncthreads();

        // Epilogue: SMEM bounce (32x33 fp32 per warp) in stage0 region.
        {
            const int sp = wid & 3;
            const int dsel = wid >> 2;
            const uint32_t epi = base + (uint32_t)wid * 4224u;  // 8*4224 = 33792 < 64KB
            const int mbase = m0 + dsel * 128 + sp * 32;
            const uint32_t dbase = tmem + (uint32_t)(dsel * 256);

            for (int cc = 0; cc < BN; cc += 32) {
                uint32_t d[32];
                TCGEN05_LD_32X32B_X32(d, dbase + (uint32_t)cc);
                TCGEN05_WAIT_LD();
                #pragma unroll
                for (int j = 0; j < 32; j++) {
                    float v = __uint_as_float(d[j]) + __ldg(bias + n0 + cc + j);
                    asm volatile("st.shared.f32 [%0], %1;"
                                 :: "r"(epi + ((uint32_t)lid * 33u + (uint32_t)j) * 4u), "f"(v) : "memory");
                }
                __syncwarp();
                #pragma unroll
                for (int r = 0; r < 32; r++) {
                    float v;
                    asm volatile("ld.shared.f32 %0, [%1];"
                                 : "=f"(v) : "r"(epi + ((uint32_t)r * 33u + (uint32_t)lid) * 4u));
                    out[(size_t)(mbase + r) * N_DIM + (size_t)(n0 + cc + lid)] = v;
                }
                __syncwarp();
            }
        }
        __syncthreads();   // epilogue SMEM reuse done before next tile's prologue / slot write
    }

    __syncthreads();
    if (wid == 0) {
        TCGEN05_RELINQUISH();
        TCGEN05_DEALLOC(tmem, 512);
    }

#else
    // ================= mma.sync fallback (baseline pass; not expected to run) =========
    __nv_bfloat16* fA = reinterpret_cast<__nv_bfloat16*>(smem_raw);   // [128][64]
    __nv_bfloat16* fB = fA + 128 * 64;                                 // [128][64]

    const int t = blockIdx.x;
    const int m0 = (t / NT_X) * BM;
    const int n0 = (t % NT_X) * BN;

    const int wr = wid >> 1;
    const int wc = wid & 1;
    const int lq = lid >> 2;
    const int lr = (lid & 3) * 2;

    for (int sub = 0; sub < 4; sub++) {
        const int sm0 = m0 + (sub >> 1) * 128;
        const int sn0 = n0 + (sub & 1) * 128;

        float acc[16][4];
        #pragma unroll
        for (int i = 0; i < 16; i++)
            #pragma unroll
            for (int j = 0; j < 4; j++) acc[i][j] = 0.0f;

        for (int c = 0; c < NCHUNK; c++) {
            __syncthreads();
            #pragma unroll
            for (int j = 0; j < 4; j++) {
                int idx = j * GEMM_THREADS + tid;
                int row = idx >> 3;
                int seg = idx & 7;
                reinterpret_cast<uint4*>(fA)[row * 8 + seg] =
                    *(reinterpret_cast<const uint4*>(A + (size_t)(sm0 + row) * K_DIM + c * BK) + seg);
                reinterpret_cast<uint4*>(fB)[row * 8 + seg] =
                    *(reinterpret_cast<const uint4*>(B + (size_t)(sn0 + row) * K_DIM + c * BK) + seg);
            }
            __syncthreads();

            #pragma unroll
            for (int kk = 0; kk < 4; kk++) {
                const int kb = kk * 16;
                uint32_t afr[2][4];
                #pragma unroll
                for (int mt = 0; mt < 2; mt++) {
                    int ar = wr * 32 + mt * 16 + lq;
                    int ac = kb + lr;
                    afr[mt][0] = *reinterpret_cast<const uint32_t*>(fA + ar * 64 + ac);
                    afr[mt][1] = *reinterpret_cast<const uint32_t*>(fA + (ar + 8) * 64 + ac);
                    afr[mt][2] = *reinterpret_cast<const uint32_t*>(fA + ar * 64 + ac + 8);
                    afr[mt][3] = *reinterpret_cast<const uint32_t*>(fA + (ar + 8) * 64 + ac + 8);
                }
                uint32_t bfr[8][2];
                #pragma unroll
                for (int nt = 0; nt < 8; nt++) {
                    int bn = wc * 64 + nt * 8 + lq;
                    int bk = kb + lr;
                    bfr[nt][0] = *reinterpret_cast<const uint32_t*>(fB + bn * 64 + bk);
                    bfr[nt][1] = *reinterpret_cast<const uint32_t*>(fB + bn * 64 + bk + 8);
                }
                #pragma unroll
                for (int mt = 0; mt < 2; mt++)
                    #pragma unroll
                    for (int nt = 0; nt < 8; nt++) {
                        float* d = acc[mt * 8 + nt];
                        asm volatile(
                            "mma.sync.aligned.m16n8k16.row.col.f32.bf16.bf16.f32 "
                            "{%0,%1,%2,%3}, {%4,%5,%6,%7}, {%8,%9}, {%0,%1,%2,%3};"
                            : "+f"(d[0]), "+f"(d[1]), "+f"(d[2]), "+f"(d[3])
                            : "r"(afr[mt][0]), "r"(afr[mt][1]), "r"(afr[mt][2]), "r"(afr[mt][3]),
                              "r"(bfr[nt][0]), "r"(bfr[nt][1]));
                    }
            }
        }

        #pragma unroll
        for (int mt = 0; mt < 2; mt++) {
            #pragma unroll
            for (int nt = 0; nt < 8; nt++) {
                const float* d = acc[mt * 8 + nt];
                int r0 = sm0 + wr * 32 + mt * 16 + lq;
                int col = sn0 + wc * 64 + nt * 8 + lr;
                float b0 = __ldg(bias + col);
                float b1 = __ldg(bias + col + 1);
                out[(size_t)r0 * N_DIM + col]            = d[0] + b0;
                out[(size_t)r0 * N_DIM + col + 1]        = d[1] + b1;
                out[(size_t)(r0 + 8) * N_DIM + col]      = d[2] + b0;
                out[(size_t)(r0 + 8) * N_DIM + col + 1]  = d[3] + b1;
            }
        }
        __syncthreads();
    }
#endif
}

// ---------------- launcher ----------------
extern "C" void kernel_launch(void* const* d_in, const int* in_sizes, int n_in,
                              void* d_out, int out_size) {
    (void)in_sizes; (void)n_in; (void)out_size;
    const float* x    = (const float*)d_in[0];   // [8192, 4096]
    const float* w    = (const float*)d_in[1];   // [4096, 4096]
    const float* bias = (const float*)d_in[2];   // [4096]
    float* out = (float*)d_out;                  // [8192, 4096]

    __nv_bfloat16 *xq = nullptr, *wq = nullptr;
    cudaGetSymbolAddress((void**)&xq, g_xq);
    cudaGetSymbolAddress((void**)&wq, g_wq);

    const int xg = M_DIM * K_DIM / 16;
    const int wg = N_DIM * K_DIM / 16;
    dequant_kernel<<<xg / 256, 256>>>(x, xq, xg);
    dequant_kernel<<<wg / 256, 256>>>(w, wq, wg);

    reset_ctr_kernel<<<1, 1>>>();

    cudaFuncSetAttribute(gemm_fp4, cudaFuncAttributeMaxDynamicSharedMemorySize, GEMM_SMEM_BYTES);
    // Persistent-with-stealing: resident CTAs drain the tile counter; late CTAs
    // (scheduled only as SMs free up) see an exhausted counter and exit.
    gemm_fp4<<<NTILES, GEMM_THREADS, GEMM_SMEM_BYTES>>>(xq, wq, bias, out);
}

// round 5
// speedup vs baseline: 1.6485x; 1.1254x over previous
#include <cuda_runtime.h>
#include <cuda.h>
#include <cuda_bf16.h>
#include <cuda_fp8.h>
#include <stdint.h>

#define M_DIM 8192
#define K_DIM 4096
#define N_DIM 4096

// Arch-specific feature gate: tcgen05 PTX may only be emitted in sm_103a /
// sm_103f passes. In the baseline compute_103 pass these macros are all
// undefined and the mma.sync fallback body is compiled instead.
#if defined(__CUDA_ARCH__) && (__CUDA_ARCH__ >= 1000) && \
    (defined(__CUDA_ARCH_FEAT_SM103_ALL) || defined(__CUDA_ARCH_FEAT_SM100_ALL) || \
     defined(__CUDA_ARCH_SPECIFIC__) || defined(__CUDA_ARCH_FAMILY_SPECIFIC__))
#define USE_TCGEN05 1
#else
#define USE_TCGEN05 0
#endif

// ---------------- scratch (allowed: __device__ globals) ----------------
__device__ __nv_bfloat16 g_xq[(size_t)M_DIM * K_DIM];   // 64 MB
__device__ __nv_bfloat16 g_wq[(size_t)N_DIM * K_DIM];   // 32 MB
__device__ unsigned int g_tile_ctr;

__global__ void reset_ctr_kernel() { g_tile_ctr = 0u; }

// ---------------- PTX helpers ----------------
__device__ __forceinline__ uint32_t smem_u32(const void* p) {
    uint32_t a;
    asm("{ .reg .u64 t; cvta.to.shared.u64 t, %1; cvt.u32.u64 %0, t; }"
        : "=r"(a) : "l"(p));
    return a;
}

#if USE_TCGEN05
__device__ __forceinline__ uint32_t elect_one_pred() {
    uint32_t pred;
    asm volatile(
        "{\n\t.reg .pred p;\n\t"
        "elect.sync _|p, 0xFFFFFFFF;\n\t"
        "selp.b32 %0, 1, 0, p;\n\t}"
        : "=r"(pred));
    return pred;
}

#define MBARRIER_INIT(addr, cnt) \
    asm volatile("mbarrier.init.shared.b64 [%0], %1;" :: "r"((uint32_t)(addr)), "r"((uint32_t)(cnt)) : "memory")

#define MBARRIER_EXPECT_TX(addr, bytes) \
    asm volatile("mbarrier.arrive.expect_tx.shared.b64 _, [%0], %1;" \
        :: "r"((uint32_t)(addr)), "r"((uint32_t)(bytes)) : "memory")

#define MBARRIER_WAIT_PARITY(mbar_smem_addr, phase_parity) do { \
    uint32_t _mbar = (uint32_t)(mbar_smem_addr); \
    uint32_t _parity = (uint32_t)(phase_parity); \
    uint32_t _done; \
    asm volatile( \
        "{\n\t.reg .pred p;\n\t" \
        "mbarrier.try_wait.parity.acquire.cta.shared::cta.b64 p, [%1], %2;\n\t" \
        "selp.b32 %0, 1, 0, p;\n\t}" \
        : "=r"(_done) : "r"(_mbar), "r"(_parity) : "memory"); \
    if (!_done) { \
        asm volatile( \
            "{\n\t.reg .pred P1;\n\t" \
            "WAIT_LOOP_%=:\n\t" \
            "mbarrier.try_wait.parity.acquire.cta.shared::cta.b64 P1, [%0], %1, 0x989680;\n\t" \
            "@P1 bra.uni WAIT_DONE_%=;\n\t" \
            "bra.uni WAIT_LOOP_%=;\n\t" \
            "WAIT_DONE_%=:\n\t}" \
            :: "r"(_mbar), "r"(_parity) : "memory"); \
    } \
} while (0)

#define TMA_LOAD_2D(smem_addr, map_ptr, cx, cy, mbar) \
    asm volatile( \
        "cp.async.bulk.tensor.2d.shared::cta.global.tile.mbarrier::complete_tx::bytes " \
        "[%0], [%1, {%2, %3}], [%4];" \
        :: "r"((uint32_t)(smem_addr)), "l"(map_ptr), "r"((int)(cx)), "r"((int)(cy)), \
           "r"((uint32_t)(mbar)) : "memory")

#define TCGEN05_ALLOC(smem_result_addr, nCols) \
    asm volatile("tcgen05.alloc.cta_group::1.sync.aligned.shared::cta.b32 [%0], %1;" \
        :: "r"((uint32_t)(smem_result_addr)), "r"((uint32_t)(nCols)) : "memory")

#define TCGEN05_DEALLOC(tmem_addr, nCols) \
    asm volatile("tcgen05.dealloc.cta_group::1.sync.aligned.b32 %0, %1;" \
        :: "r"(tmem_addr), "r"((uint32_t)(nCols)))

#define TCGEN05_RELINQUISH() \
    asm volatile("tcgen05.relinquish_alloc_permit.cta_group::1.sync.aligned;")

#define TCGEN05_COMMIT(mbar_smem_addr) \
    asm volatile("tcgen05.commit.cta_group::1.mbarrier::arrive::one.shared::cluster.b64 [%0];" \
        :: "r"((uint32_t)(mbar_smem_addr)) : "memory")

#define TCGEN05_WAIT_LD() \
    asm volatile("tcgen05.wait::ld.sync.aligned;" ::: "memory")

#define TCGEN05_FENCE_AFTER() \
    asm volatile("tcgen05.fence::after_thread_sync;" ::: "memory")

#define TCGEN05_FENCE_BEFORE() \
    asm volatile("tcgen05.fence::before_thread_sync;" ::: "memory")

#define TCGEN05_LD_32X32B_X32(r, tmem_addr) \
    asm volatile( \
        "tcgen05.ld.sync.aligned.32x32b.x32.b32 " \
        "{%0, %1, %2, %3, %4, %5, %6, %7, " \
        " %8, %9, %10, %11, %12, %13, %14, %15, " \
        " %16, %17, %18, %19, %20, %21, %22, %23, " \
        " %24, %25, %26, %27, %28, %29, %30, %31}, [%32];" \
        : "=r"((r)[0]),  "=r"((r)[1]),  "=r"((r)[2]),  "=r"((r)[3]), \
          "=r"((r)[4]),  "=r"((r)[5]),  "=r"((r)[6]),  "=r"((r)[7]), \
          "=r"((r)[8]),  "=r"((r)[9]),  "=r"((r)[10]), "=r"((r)[11]), \
          "=r"((r)[12]), "=r"((r)[13]), "=r"((r)[14]), "=r"((r)[15]), \
          "=r"((r)[16]), "=r"((r)[17]), "=r"((r)[18]), "=r"((r)[19]), \
          "=r"((r)[20]), "=r"((r)[21]), "=r"((r)[22]), "=r"((r)[23]), \
          "=r"((r)[24]), "=r"((r)[25]), "=r"((r)[26]), "=r"((r)[27]), \
          "=r"((r)[28]), "=r"((r)[29]), "=r"((r)[30]), "=r"((r)[31]) \
        : "r"(tmem_addr))

__device__ __forceinline__ uint64_t make_desc(uint32_t addr) {
    // SW128, Blackwell version=1, LBO=1 (16B), SBO=64 (1024B)
    const uint64_t base = (2ull << 61) | (1ull << 46) | (64ull << 32) | (1ull << 16);
    return base | ((uint64_t)(addr >> 4) & 0x3FFFull);
}

__device__ __forceinline__ void mma_f16_ss(uint32_t d, uint64_t a_desc, uint64_t b_desc,
                                           uint32_t idesc, uint32_t acc) {
    asm volatile(
        "{\n\t.reg .pred p;\n\t"
        "setp.ne.u32 p, %5, 0;\n\t"
        "tcgen05.mma.cta_group::1.kind::f16 [%0], %1, %2, %3, {%4, %4, %4, %4}, p;\n\t}"
        :: "r"(d), "l"(a_desc), "l"(b_desc), "r"(idesc), "r"(0u), "r"(acc)
        : "memory");
}
#endif  // USE_TCGEN05

// ---------------- dequant (fake-quant fp32 -> exact bf16) ----------------
// Division-free bucketing: |v|/scale < T  <=>  |v| < T*scale for scale>0,
// with T*scale exact in fp32 (<=3 mantissa bits each side).
__global__ void __launch_bounds__(256) dequant_kernel(const float* __restrict__ in,
                                                      __nv_bfloat16* __restrict__ out,
                                                      int ngroups) {
    int g = blockIdx.x * blockDim.x + threadIdx.x;
    if (g >= ngroups) return;

    const float4* p = reinterpret_cast<const float4*>(in) + (size_t)g * 4;
    float v[16];
    {
        float4 t0 = p[0], t1 = p[1], t2 = p[2], t3 = p[3];
        v[0]=t0.x; v[1]=t0.y; v[2]=t0.z;  v[3]=t0.w;
        v[4]=t1.x; v[5]=t1.y; v[6]=t1.z;  v[7]=t1.w;
        v[8]=t2.x; v[9]=t2.y; v[10]=t2.z; v[11]=t2.w;
        v[12]=t3.x; v[13]=t3.y; v[14]=t3.z; v[15]=t3.w;
    }

    float amax = 0.0f;
    #pragma unroll
    for (int i = 0; i < 16; i++) amax = fmaxf(amax, fabsf(v[i]));

    float sraw = __fdiv_rn(amax, 6.0f);
    __nv_fp8_e4m3 s8(sraw);
    float scale = float(s8);

    union { __nv_bfloat16 h[16]; uint4 u[2]; } pk;
    if (scale > 0.0f) {
        const float t0 = 0.25f * scale, t1 = 0.75f * scale, t2 = 1.25f * scale,
                    t3 = 1.75f * scale, t4 = 2.5f * scale,  t5 = 3.5f * scale,
                    t6 = 5.0f * scale;
        const float q1 = 0.5f * scale, q2 = scale,        q3 = 1.5f * scale,
                    q4 = 2.0f * scale, q5 = 3.0f * scale, q6 = 4.0f * scale,
                    q7 = 6.0f * scale;
        #pragma unroll
        for (int i = 0; i < 16; i++) {
            float a = fabsf(v[i]);
            float r;
            if      (a < t0) r = 0.0f;
            else if (a < t1) r = q1;
            else if (a < t2) r = q2;
            else if (a < t3) r = q3;
            else if (a < t4) r = q4;
            else if (a < t5) r = q5;
            else if (a < t6) r = q6;
            else             r = q7;
            pk.h[i] = __float2bfloat16(v[i] < 0.0f ? -r : r);  // exact in bf16
        }
    } else {
        #pragma unroll
        for (int i = 0; i < 16; i++) pk.h[i] = __float2bfloat16(0.0f);
    }

    uint4* q = reinterpret_cast<uint4*>(out) + (size_t)g * 2;
    q[0] = pk.u[0];
    q[1] = pk.u[1];
}

// ---------------- GEMM ----------------
#define BM 256
#define BN 256
#define BK 64
#define GEMM_THREADS 256
#define NCHUNK (K_DIM / BK)          // 64
#define NT_X (N_DIM / BN)            // 16
#define NTILES ((M_DIM / BM) * NT_X) // 512
#define NSTAGE 3
#define STAGE_BYTES 65536            // A 32KB + B 32KB per stage
#define STAGE_TX 65536

// idesc: dtype F32, a/b BF16, N=128, M=128
#define GEMM_IDESC ((1u << 4) | (1u << 7) | (1u << 10) | ((128u / 8u) << 17) | ((128u / 16u) << 24))

#define HDR_OFF (NSTAGE * STAGE_BYTES)
#define GEMM_SMEM_BYTES (HDR_OFF + 128 + 1024)

__global__ void __launch_bounds__(GEMM_THREADS, 1)
gemm_fp4(const __grid_constant__ CUtensorMap mapA,
         const __grid_constant__ CUtensorMap mapB,
         const __nv_bfloat16* __restrict__ A,   // [M, K] (fallback path only)
         const __nv_bfloat16* __restrict__ B,   // [N, K] (fallback path only)
         const float* __restrict__ bias,        // [N]
         float* __restrict__ out)               // [M, N]
{
    extern __shared__ char smem_raw[];
    const int tid = threadIdx.x;
    const int wid = tid >> 5;
    const int lid = tid & 31;

#if USE_TCGEN05
    // ================= persistent warp-specialized tcgen05 + TMA =================
    const uint32_t base = (smem_u32(smem_raw) + 1023u) & ~1023u;
    const uint32_t hdr = base + HDR_OFF;
    const uint32_t tmem_ptr_addr = hdr;          // 8B
    const uint32_t full0  = hdr + 16u;           // full[s]  = hdr+16 + 8s
    const uint32_t empty0 = hdr + 40u;           // empty[s] = hdr+40 + 8s
    const uint32_t doneb  = hdr + 64u;           // per-tile "all MMAs done"
    const uint32_t slot   = hdr + 72u;           // next-tile broadcast

    if (wid == 0) TCGEN05_ALLOC(tmem_ptr_addr, 512);
    if (tid == 0) {
        #pragma unroll
        for (int s = 0; s < 3; s++) {
            MBARRIER_INIT(full0  + (uint32_t)s * 8u, 1);
            MBARRIER_INIT(empty0 + (uint32_t)s * 8u, 1);
        }
        MBARRIER_INIT(doneb, 1);
        unsigned int t0 = atomicAdd(&g_tile_ctr, 1u);
        asm volatile("st.shared.u32 [%0], %1;" :: "r"(slot), "r"(t0) : "memory");
    }
    __syncthreads();

    uint32_t tmem;
    asm volatile("ld.shared.b32 %0, [%1];" : "=r"(tmem) : "r"(tmem_ptr_addr));
    uint32_t t;
    asm volatile("ld.shared.u32 %0, [%1];" : "=r"(t) : "r"(slot));

    uint32_t n0c = 0, n1c = 0, n2c = 0;   // per-stage use counters
    uint32_t tile_cnt = 0;                // per-CTA processed-tile counter
    int s_cur = 0;                        // rotating stage, continuous across tiles
    bool first = true;

    while (t < NTILES) {
        // claim next tile; sync also orders prev-tile TMEM reads before this tile's MMAs
        if (tid == 0) {
            unsigned int tn_ = atomicAdd(&g_tile_ctr, 1u);
            asm volatile("st.shared.u32 [%0], %1;" :: "r"(slot), "r"(tn_) : "memory");
        }
        __syncthreads();
        uint32_t tn;
        asm volatile("ld.shared.u32 %0, [%1];" : "=r"(tn) : "r"(slot));

        const int m0  = (int)(t / NT_X) * BM;
        const int nn0 = (int)(t % NT_X) * BN;
        const int m0n  = (int)(tn / NT_X) * BM;   // valid only if tn < NTILES
        const int nn0n = (int)(tn % NT_X) * BN;

        if (first) {
            if (wid == 1 && elect_one_pred()) {
                #pragma unroll
                for (int p = 0; p < 3; p++) {
                    const uint32_t fb = full0 + (uint32_t)p * 8u;
                    MBARRIER_EXPECT_TX(fb, STAGE_TX);
                    TMA_LOAD_2D(base + (uint32_t)p * STAGE_BYTES,          &mapA, p * BK, m0,  fb);
                    TMA_LOAD_2D(base + (uint32_t)p * STAGE_BYTES + 32768u, &mapB, p * BK, nn0, fb);
                }
            }
            first = false;
        }

        for (int c = 0; c < NCHUNK; c++) {
            const int s = s_cur;
            s_cur = (s_cur == 2) ? 0 : s_cur + 1;
            const uint32_t ncur = (s == 0) ? n0c : (s == 1) ? n1c : n2c;
            const uint32_t par = ncur & 1u;
            const uint32_t sa = base + (uint32_t)s * STAGE_BYTES;
            const uint32_t fb = full0 + (uint32_t)s * 8u;
            const uint32_t eb = empty0 + (uint32_t)s * 8u;

            if (wid == 0) {
                if (elect_one_pred()) {
                    MBARRIER_WAIT_PARITY(fb, par);     // lag<=1 per stage: alias-safe
                    const uint64_t ad0 = make_desc(sa);
                    const uint64_t ad1 = make_desc(sa + 16384u);
                    const uint64_t bd0 = make_desc(sa + 32768u);
                    const uint64_t bd1 = make_desc(sa + 49152u);
                    #pragma unroll
                    for (int ks = 0; ks < 4; ks++) {
                        const uint32_t acc = (c > 0 || ks > 0) ? 1u : 0u;
                        const uint64_t kadd = (uint64_t)(ks * 2);
                        mma_f16_ss(tmem + 0u,   ad0 + kadd, bd0 + kadd, GEMM_IDESC, acc);
                        mma_f16_ss(tmem + 128u, ad0 + kadd, bd1 + kadd, GEMM_IDESC, acc);
                        mma_f16_ss(tmem + 256u, ad1 + kadd, bd0 + kadd, GEMM_IDESC, acc);
                        mma_f16_ss(tmem + 384u, ad1 + kadd, bd1 + kadd, GEMM_IDESC, acc);
                    }
                    TCGEN05_COMMIT(eb);
                }
            } else if (wid == 1) {
                if (elect_one_pred()) {
                    // fill chunk c+3 (this tile, or next tile's chunk c+3-64)
                    int kx, ya, yb;
                    bool valid;
                    if (c + 3 < NCHUNK) {
                        valid = true; kx = (c + 3) * BK; ya = m0; yb = nn0;
                    } else if (tn < NTILES) {
                        valid = true; kx = (c + 3 - NCHUNK) * BK; ya = m0n; yb = nn0n;
                    } else {
                        valid = false; kx = 0; ya = 0; yb = 0;
                    }
                    if (valid) {
                        MBARRIER_WAIT_PARITY(eb, par);   // MMA(c) done reading stage s; lag<=1
                        MBARRIER_EXPECT_TX(fb, STAGE_TX);
                        TMA_LOAD_2D(sa,           &mapA, kx, ya, fb);
                        TMA_LOAD_2D(sa + 32768u,  &mapB, kx, yb, fb);
                    }
                }
            }
            if (s == 0) n0c++; else if (s == 1) n1c++; else n2c++;
        }

        // Tile-done barrier: ONE commit after all 64 chunks (MMA execution is
        // in-order, so this fires only after every MMA of this tile completes).
        // Alias-safe: all warps are in the same tile iteration (loop-top
        // __syncthreads), so completed phases at this wait are {tile_cnt-1, tile_cnt}.
        if (wid == 0 && elect_one_pred()) TCGEN05_COMMIT(doneb);
        MBARRIER_WAIT_PARITY(doneb, tile_cnt & 1u);
        tile_cnt++;
        TCGEN05_FENCE_AFTER();

        // Epilogue: direct coalesced stores; thread owns row m, 32 consecutive
        // cols (one 128B line) per block.
        {
            const int sp = wid & 3;
            const int dsel = wid >> 2;
            const int m = m0 + dsel * 128 + sp * 32 + lid;
            const uint32_t dbase = tmem + (uint32_t)(dsel * 256);
            float* orow = out + (size_t)m * N_DIM + nn0;

            for (int cc = 0; cc < BN; cc += 32) {
                uint32_t d[32];
                TCGEN05_LD_32X32B_X32(d, dbase + (uint32_t)cc);
                TCGEN05_WAIT_LD();
                const float4* b4 = reinterpret_cast<const float4*>(bias + nn0 + cc);
                float4* o4 = reinterpret_cast<float4*>(orow + cc);
                #pragma unroll
                for (int q = 0; q < 8; q++) {
                    float4 bv = __ldg(b4 + q);
                    float4 ov;
                    ov.x = __uint_as_float(d[q * 4 + 0]) + bv.x;
                    ov.y = __uint_as_float(d[q * 4 + 1]) + bv.y;
                    ov.z = __uint_as_float(d[q * 4 + 2]) + bv.z;
                    ov.w = __uint_as_float(d[q * 4 + 3]) + bv.w;
                    o4[q] = ov;
                }
            }
            TCGEN05_FENCE_BEFORE();
        }

        t = tn;
    }

    __syncthreads();
    if (wid == 0) {
        TCGEN05_RELINQUISH();
        TCGEN05_DEALLOC(tmem, 512);
    }

#else
    // ================= mma.sync fallback (baseline pass; not expected to run) ======
    __nv_bfloat16* fA = reinterpret_cast<__nv_bfloat16*>(smem_raw);   // [128][64]
    __nv_bfloat16* fB = fA + 128 * 64;                                 // [128][64]

    const int tt = blockIdx.x;
    const int m0 = (tt / NT_X) * BM;
    const int n0 = (tt % NT_X) * BN;

    const int wr = wid >> 1;
    const int wc = wid & 1;
    const int lq = lid >> 2;
    const int lr = (lid & 3) * 2;

    for (int sub = 0; sub < 4; sub++) {
        const int sm0 = m0 + (sub >> 1) * 128;
        const int sn0 = n0 + (sub & 1) * 128;

        float acc[16][4];
        #pragma unroll
        for (int i = 0; i < 16; i++)
            #pragma unroll
            for (int j = 0; j < 4; j++) acc[i][j] = 0.0f;

        for (int c = 0; c < NCHUNK; c++) {
            __syncthreads();
            #pragma unroll
            for (int j = 0; j < 4; j++) {
                int idx = j * GEMM_THREADS + tid;
                int row = idx >> 3;
                int seg = idx & 7;
                reinterpret_cast<uint4*>(fA)[row * 8 + seg] =
                    *(reinterpret_cast<const uint4*>(A + (size_t)(sm0 + row) * K_DIM + c * BK) + seg);
                reinterpret_cast<uint4*>(fB)[row * 8 + seg] =
                    *(reinterpret_cast<const uint4*>(B + (size_t)(sn0 + row) * K_DIM + c * BK) + seg);
            }
            __syncthreads();

            #pragma unroll
            for (int kk = 0; kk < 4; kk++) {
                const int kb = kk * 16;
                uint32_t afr[2][4];
                #pragma unroll
                for (int mt = 0; mt < 2; mt++) {
                    int ar = wr * 32 + mt * 16 + lq;
                    int ac = kb + lr;
                    afr[mt][0] = *reinterpret_cast<const uint32_t*>(fA + ar * 64 + ac);
                    afr[mt][1] = *reinterpret_cast<const uint32_t*>(fA + (ar + 8) * 64 + ac);
                    afr[mt][2] = *reinterpret_cast<const uint32_t*>(fA + ar * 64 + ac + 8);
                    afr[mt][3] = *reinterpret_cast<const uint32_t*>(fA + (ar + 8) * 64 + ac + 8);
                }
                uint32_t bfr[8][2];
                #pragma unroll
                for (int nt = 0; nt < 8; nt++) {
                    int bn = wc * 64 + nt * 8 + lq;
                    int bk = kb + lr;
                    bfr[nt][0] = *reinterpret_cast<const uint32_t*>(fB + bn * 64 + bk);
                    bfr[nt][1] = *reinterpret_cast<const uint32_t*>(fB + bn * 64 + bk + 8);
                }
                #pragma unroll
                for (int mt = 0; mt < 2; mt++)
                    #pragma unroll
                    for (int nt = 0; nt < 8; nt++) {
                        float* d = acc[mt * 8 + nt];
                        asm volatile(
                            "mma.sync.aligned.m16n8k16.row.col.f32.bf16.bf16.f32 "
                            "{%0,%1,%2,%3}, {%4,%5,%6,%7}, {%8,%9}, {%0,%1,%2,%3};"
                            : "+f"(d[0]), "+f"(d[1]), "+f"(d[2]), "+f"(d[3])
                            : "r"(afr[mt][0]), "r"(afr[mt][1]), "r"(afr[mt][2]), "r"(afr[mt][3]),
                              "r"(bfr[nt][0]), "r"(bfr[nt][1]));
                    }
            }
        }

        #pragma unroll
        for (int mt = 0; mt < 2; mt++) {
            #pragma unroll
            for (int nt = 0; nt < 8; nt++) {
                const float* d = acc[mt * 8 + nt];
                int r0 = sm0 + wr * 32 + mt * 16 + lq;
                int col = sn0 + wc * 64 + nt * 8 + lr;
                float b0 = __ldg(bias + col);
                float b1 = __ldg(bias + col + 1);
                out[(size_t)r0 * N_DIM + col]            = d[0] + b0;
                out[(size_t)r0 * N_DIM + col + 1]        = d[1] + b1;
                out[(size_t)(r0 + 8) * N_DIM + col]      = d[2] + b0;
                out[(size_t)(r0 + 8) * N_DIM + col + 1]  = d[3] + b1;
            }
        }
        __syncthreads();
    }
#endif
}

// ---------------- host: tensormap encode via driver entry point ----------------
typedef CUresult (*PFN_encodeTiled)(
    CUtensorMap*, CUtensorMapDataType, cuuint32_t, void*,
    const cuuint64_t*, const cuuint64_t*, const cuuint32_t*, const cuuint32_t*,
    CUtensorMapInterleave, CUtensorMapSwizzle, CUtensorMapL2promotion,
    CUtensorMapFloatOOBfill);

static void encode_map(CUtensorMap* map, void* ptr, uint64_t rows, uint64_t cols_k) {
    void* p = nullptr;
    cudaDriverEntryPointQueryResult st;
    cudaGetDriverEntryPointByVersion("cuTensorMapEncodeTiled", &p, 12000,
                                     cudaEnableDefault, &st);
    PFN_encodeTiled fn = (PFN_encodeTiled)p;
    cuuint64_t dims[2]    = {cols_k, rows};
    cuuint64_t strides[1] = {cols_k * 2};          // bytes per row
    cuuint32_t box[2]     = {BK, 256};
    cuuint32_t estr[2]    = {1, 1};
    fn(map, CU_TENSOR_MAP_DATA_TYPE_BFLOAT16, 2, ptr,
       dims, strides, box, estr,
       CU_TENSOR_MAP_INTERLEAVE_NONE, CU_TENSOR_MAP_SWIZZLE_128B,
       CU_TENSOR_MAP_L2_PROMOTION_L2_128B,
       CU_TENSOR_MAP_FLOAT_OOB_FILL_NONE);
}

// ---------------- launcher ----------------
extern "C" void kernel_launch(void* const* d_in, const int* in_sizes, int n_in,
                              void* d_out, int out_size) {
    (void)in_sizes; (void)n_in; (void)out_size;
    const float* x    = (const float*)d_in[0];   // [8192, 4096]
    const float* w    = (const float*)d_in[1];   // [4096, 4096]
    const float* bias = (const float*)d_in[2];   // [4096]
    float* out = (float*)d_out;                  // [8192, 4096]

    __nv_bfloat16 *xq = nullptr, *wq = nullptr;
    cudaGetSymbolAddress((void**)&xq, g_xq);
    cudaGetSymbolAddress((void**)&wq, g_wq);

    CUtensorMap mapA, mapB;
    encode_map(&mapA, xq, M_DIM, K_DIM);
    encode_map(&mapB, wq, N_DIM, K_DIM);

    const int xg = M_DIM * K_DIM / 16;
    const int wg = N_DIM * K_DIM / 16;
    dequant_kernel<<<xg / 256, 256>>>(x, xq, xg);
    dequant_kernel<<<wg / 256, 256>>>(w, wq, wg);

    reset_ctr_kernel<<<1, 1>>>();

    cudaFuncSetAttribute(gemm_fp4, cudaFuncAttributeMaxDynamicSharedMemorySize, GEMM_SMEM_BYTES);
    gemm_fp4<<<NTILES, GEMM_THREADS, GEMM_SMEM_BYTES>>>(mapA, mapB, xq, wq, bias, out);
}

// round 6
// speedup vs baseline: 1.6808x; 1.0196x over previous
#include <cuda_runtime.h>
#include <cuda.h>
#include <cuda_bf16.h>
#include <cuda_fp8.h>
#include <stdint.h>

#define M_DIM 8192
#define K_DIM 4096
#define N_DIM 4096

// Arch-specific feature gate: tcgen05 PTX may only be emitted in sm_103a /
// sm_103f passes. In the baseline compute_103 pass these macros are all
// undefined and the mma.sync fallback body is compiled instead.
#if defined(__CUDA_ARCH__) && (__CUDA_ARCH__ >= 1000) && \
    (defined(__CUDA_ARCH_FEAT_SM103_ALL) || defined(__CUDA_ARCH_FEAT_SM100_ALL) || \
     defined(__CUDA_ARCH_SPECIFIC__) || defined(__CUDA_ARCH_FAMILY_SPECIFIC__))
#define USE_TCGEN05 1
#else
#define USE_TCGEN05 0
#endif

// ---------------- scratch (allowed: __device__ globals) ----------------
__device__ __nv_bfloat16 g_xq[(size_t)M_DIM * K_DIM];   // 64 MB
__device__ __nv_bfloat16 g_wq[(size_t)N_DIM * K_DIM];   // 32 MB
__device__ unsigned int g_tile_ctr;

__global__ void reset_ctr_kernel() { g_tile_ctr = 0u; }

// ---------------- PTX helpers ----------------
__device__ __forceinline__ uint32_t smem_u32(const void* p) {
    uint32_t a;
    asm("{ .reg .u64 t; cvta.to.shared.u64 t, %1; cvt.u32.u64 %0, t; }"
        : "=r"(a) : "l"(p));
    return a;
}

#if USE_TCGEN05
__device__ __forceinline__ uint32_t elect_one_pred() {
    uint32_t pred;
    asm volatile(
        "{\n\t.reg .pred p;\n\t"
        "elect.sync _|p, 0xFFFFFFFF;\n\t"
        "selp.b32 %0, 1, 0, p;\n\t}"
        : "=r"(pred));
    return pred;
}

#define MBARRIER_INIT(addr, cnt) \
    asm volatile("mbarrier.init.shared.b64 [%0], %1;" :: "r"((uint32_t)(addr)), "r"((uint32_t)(cnt)) : "memory")

#define MBARRIER_EXPECT_TX(addr, bytes) \
    asm volatile("mbarrier.arrive.expect_tx.shared.b64 _, [%0], %1;" \
        :: "r"((uint32_t)(addr)), "r"((uint32_t)(bytes)) : "memory")

#define MBARRIER_WAIT_PARITY(mbar_smem_addr, phase_parity) do { \
    uint32_t _mbar = (uint32_t)(mbar_smem_addr); \
    uint32_t _parity = (uint32_t)(phase_parity); \
    uint32_t _done; \
    asm volatile( \
        "{\n\t.reg .pred p;\n\t" \
        "mbarrier.try_wait.parity.acquire.cta.shared::cta.b64 p, [%1], %2;\n\t" \
        "selp.b32 %0, 1, 0, p;\n\t}" \
        : "=r"(_done) : "r"(_mbar), "r"(_parity) : "memory"); \
    if (!_done) { \
        asm volatile( \
            "{\n\t.reg .pred P1;\n\t" \
            "WAIT_LOOP_%=:\n\t" \
            "mbarrier.try_wait.parity.acquire.cta.shared::cta.b64 P1, [%0], %1, 0x989680;\n\t" \
            "@P1 bra.uni WAIT_DONE_%=;\n\t" \
            "bra.uni WAIT_LOOP_%=;\n\t" \
            "WAIT_DONE_%=:\n\t}" \
            :: "r"(_mbar), "r"(_parity) : "memory"); \
    } \
} while (0)

#define TMA_LOAD_2D(smem_addr, map_ptr, cx, cy, mbar) \
    asm volatile( \
        "cp.async.bulk.tensor.2d.shared::cta.global.tile.mbarrier::complete_tx::bytes " \
        "[%0], [%1, {%2, %3}], [%4];" \
        :: "r"((uint32_t)(smem_addr)), "l"(map_ptr), "r"((int)(cx)), "r"((int)(cy)), \
           "r"((uint32_t)(mbar)) : "memory")

#define TCGEN05_ALLOC(smem_result_addr, nCols) \
    asm volatile("tcgen05.alloc.cta_group::1.sync.aligned.shared::cta.b32 [%0], %1;" \
        :: "r"((uint32_t)(smem_result_addr)), "r"((uint32_t)(nCols)) : "memory")

#define TCGEN05_DEALLOC(tmem_addr, nCols) \
    asm volatile("tcgen05.dealloc.cta_group::1.sync.aligned.b32 %0, %1;" \
        :: "r"(tmem_addr), "r"((uint32_t)(nCols)))

#define TCGEN05_RELINQUISH() \
    asm volatile("tcgen05.relinquish_alloc_permit.cta_group::1.sync.aligned;")

#define TCGEN05_COMMIT(mbar_smem_addr) \
    asm volatile("tcgen05.commit.cta_group::1.mbarrier::arrive::one.shared::cluster.b64 [%0];" \
        :: "r"((uint32_t)(mbar_smem_addr)) : "memory")

#define TCGEN05_WAIT_LD() \
    asm volatile("tcgen05.wait::ld.sync.aligned;" ::: "memory")

#define TCGEN05_FENCE_AFTER() \
    asm volatile("tcgen05.fence::after_thread_sync;" ::: "memory")

#define TCGEN05_FENCE_BEFORE() \
    asm volatile("tcgen05.fence::before_thread_sync;" ::: "memory")

#define TCGEN05_LD_32X32B_X32(r, tmem_addr) \
    asm volatile( \
        "tcgen05.ld.sync.aligned.32x32b.x32.b32 " \
        "{%0, %1, %2, %3, %4, %5, %6, %7, " \
        " %8, %9, %10, %11, %12, %13, %14, %15, " \
        " %16, %17, %18, %19, %20, %21, %22, %23, " \
        " %24, %25, %26, %27, %28, %29, %30, %31}, [%32];" \
        : "=r"((r)[0]),  "=r"((r)[1]),  "=r"((r)[2]),  "=r"((r)[3]), \
          "=r"((r)[4]),  "=r"((r)[5]),  "=r"((r)[6]),  "=r"((r)[7]), \
          "=r"((r)[8]),  "=r"((r)[9]),  "=r"((r)[10]), "=r"((r)[11]), \
          "=r"((r)[12]), "=r"((r)[13]), "=r"((r)[14]), "=r"((r)[15]), \
          "=r"((r)[16]), "=r"((r)[17]), "=r"((r)[18]), "=r"((r)[19]), \
          "=r"((r)[20]), "=r"((r)[21]), "=r"((r)[22]), "=r"((r)[23]), \
          "=r"((r)[24]), "=r"((r)[25]), "=r"((r)[26]), "=r"((r)[27]), \
          "=r"((r)[28]), "=r"((r)[29]), "=r"((r)[30]), "=r"((r)[31]) \
        : "r"(tmem_addr))

__device__ __forceinline__ uint64_t make_desc(uint32_t addr) {
    // SW128, Blackwell version=1, LBO=1 (16B), SBO=64 (1024B)
    const uint64_t base = (2ull << 61) | (1ull << 46) | (64ull << 32) | (1ull << 16);
    return base | ((uint64_t)(addr >> 4) & 0x3FFFull);
}

__device__ __forceinline__ void mma_f16_ss(uint32_t d, uint64_t a_desc, uint64_t b_desc,
                                           uint32_t idesc, uint32_t acc) {
    asm volatile(
        "{\n\t.reg .pred p;\n\t"
        "setp.ne.u32 p, %5, 0;\n\t"
        "tcgen05.mma.cta_group::1.kind::f16 [%0], %1, %2, %3, {%4, %4, %4, %4}, p;\n\t}"
        :: "r"(d), "l"(a_desc), "l"(b_desc), "r"(idesc), "r"(0u), "r"(acc)
        : "memory");
}
#endif  // USE_TCGEN05

// ---------------- dequant (fake-quant fp32 -> exact bf16) ----------------
// Division-free bucketing: |v|/scale < T  <=>  |v| < T*scale for scale>0,
// with T*scale exact in fp32 (<=3 mantissa bits each side).
__global__ void __launch_bounds__(256) dequant_kernel(const float* __restrict__ in,
                                                      __nv_bfloat16* __restrict__ out,
                                                      int ngroups) {
    int g = blockIdx.x * blockDim.x + threadIdx.x;
    if (g >= ngroups) return;

    const float4* p = reinterpret_cast<const float4*>(in) + (size_t)g * 4;
    float v[16];
    {
        float4 t0 = p[0], t1 = p[1], t2 = p[2], t3 = p[3];
        v[0]=t0.x; v[1]=t0.y; v[2]=t0.z;  v[3]=t0.w;
        v[4]=t1.x; v[5]=t1.y; v[6]=t1.z;  v[7]=t1.w;
        v[8]=t2.x; v[9]=t2.y; v[10]=t2.z; v[11]=t2.w;
        v[12]=t3.x; v[13]=t3.y; v[14]=t3.z; v[15]=t3.w;
    }

    float amax = 0.0f;
    #pragma unroll
    for (int i = 0; i < 16; i++) amax = fmaxf(amax, fabsf(v[i]));

    float sraw = __fdiv_rn(amax, 6.0f);
    __nv_fp8_e4m3 s8(sraw);
    float scale = float(s8);

    union { __nv_bfloat16 h[16]; uint4 u[2]; } pk;
    if (scale > 0.0f) {
        const float t0 = 0.25f * scale, t1 = 0.75f * scale, t2 = 1.25f * scale,
                    t3 = 1.75f * scale, t4 = 2.5f * scale,  t5 = 3.5f * scale,
                    t6 = 5.0f * scale;
        const float q1 = 0.5f * scale, q2 = scale,        q3 = 1.5f * scale,
                    q4 = 2.0f * scale, q5 = 3.0f * scale, q6 = 4.0f * scale,
                    q7 = 6.0f * scale;
        #pragma unroll
        for (int i = 0; i < 16; i++) {
            float a = fabsf(v[i]);
            float r;
            if      (a < t0) r = 0.0f;
            else if (a < t1) r = q1;
            else if (a < t2) r = q2;
            else if (a < t3) r = q3;
            else if (a < t4) r = q4;
            else if (a < t5) r = q5;
            else if (a < t6) r = q6;
            else             r = q7;
            pk.h[i] = __float2bfloat16(v[i] < 0.0f ? -r : r);  // exact in bf16
        }
    } else {
        #pragma unroll
        for (int i = 0; i < 16; i++) pk.h[i] = __float2bfloat16(0.0f);
    }

    uint4* q = reinterpret_cast<uint4*>(out) + (size_t)g * 2;
    q[0] = pk.u[0];
    q[1] = pk.u[1];
}

// ---------------- GEMM ----------------
#define BM 256
#define BN 256
#define BK 64
#define GEMM_THREADS 256
#define NCHUNK (K_DIM / BK)          // 64
#define NT_X (N_DIM / BN)            // 16
#define NTILES ((M_DIM / BM) * NT_X) // 512
#define NSTAGE 3
#define STAGE_BYTES 65536            // A 32KB + B 32KB per stage
#define STAGE_TX 65536

// idesc: dtype F32, a/b BF16, N=128, M=128
#define GEMM_IDESC ((1u << 4) | (1u << 7) | (1u << 10) | ((128u / 8u) << 17) | ((128u / 16u) << 24))

#define HDR_OFF (NSTAGE * STAGE_BYTES)
#define GEMM_SMEM_BYTES (HDR_OFF + 128 + 1024)

__global__ void __launch_bounds__(GEMM_THREADS, 1)
gemm_fp4(const __grid_constant__ CUtensorMap mapA,
         const __grid_constant__ CUtensorMap mapB,
         const __nv_bfloat16* __restrict__ A,   // [M, K] (fallback path only)
         const __nv_bfloat16* __restrict__ B,   // [N, K] (fallback path only)
         const float* __restrict__ bias,        // [N]
         float* __restrict__ out)               // [M, N]
{
    extern __shared__ char smem_raw[];
    const int tid = threadIdx.x;
    const int wid = tid >> 5;
    const int lid = tid & 31;

#if USE_TCGEN05
    // ================= persistent warp-specialized tcgen05 + TMA =================
    const uint32_t base = (smem_u32(smem_raw) + 1023u) & ~1023u;
    const uint32_t hdr = base + HDR_OFF;
    const uint32_t tmem_ptr_addr = hdr;          // 8B
    const uint32_t full0  = hdr + 16u;           // full[s]  = hdr+16 + 8s
    const uint32_t empty0 = hdr + 40u;           // empty[s] = hdr+40 + 8s
    const uint32_t doneb  = hdr + 64u;           // per-tile "all MMAs done"
    const uint32_t slot   = hdr + 72u;           // next-tile broadcast

    if (wid == 0) TCGEN05_ALLOC(tmem_ptr_addr, 512);
    if (tid == 0) {
        #pragma unroll
        for (int s = 0; s < 3; s++) {
            MBARRIER_INIT(full0  + (uint32_t)s * 8u, 1);
            MBARRIER_INIT(empty0 + (uint32_t)s * 8u, 1);
        }
        MBARRIER_INIT(doneb, 1);
        unsigned int t0 = atomicAdd(&g_tile_ctr, 1u);
        asm volatile("st.shared.u32 [%0], %1;" :: "r"(slot), "r"(t0) : "memory");
    }
    __syncthreads();

    uint32_t tmem;
    asm volatile("ld.shared.b32 %0, [%1];" : "=r"(tmem) : "r"(tmem_ptr_addr));
    uint32_t t;
    asm volatile("ld.shared.u32 %0, [%1];" : "=r"(t) : "r"(slot));

    uint32_t n0c = 0, n1c = 0, n2c = 0;   // per-stage use counters
    uint32_t tile_cnt = 0;                // per-CTA processed-tile counter
    int s_cur = 0;                        // rotating stage, continuous across tiles
    bool first = true;

    while (t < NTILES) {
        // claim next tile; sync also orders prev-tile TMEM reads before this tile's MMAs
        if (tid == 0) {
            unsigned int tn_ = atomicAdd(&g_tile_ctr, 1u);
            asm volatile("st.shared.u32 [%0], %1;" :: "r"(slot), "r"(tn_) : "memory");
        }
        __syncthreads();
        uint32_t tn;
        asm volatile("ld.shared.u32 %0, [%1];" : "=r"(tn) : "r"(slot));

        const int m0  = (int)(t / NT_X) * BM;
        const int nn0 = (int)(t % NT_X) * BN;
        const int m0n  = (int)(tn / NT_X) * BM;   // valid only if tn < NTILES
        const int nn0n = (int)(tn % NT_X) * BN;

        if (first) {
            if (wid == 1 && elect_one_pred()) {
                #pragma unroll
                for (int p = 0; p < 3; p++) {
                    const uint32_t fb = full0 + (uint32_t)p * 8u;
                    MBARRIER_EXPECT_TX(fb, STAGE_TX);
                    TMA_LOAD_2D(base + (uint32_t)p * STAGE_BYTES,          &mapA, p * BK, m0,  fb);
                    TMA_LOAD_2D(base + (uint32_t)p * STAGE_BYTES + 32768u, &mapB, p * BK, nn0, fb);
                }
            }
            first = false;
        }

        for (int c = 0; c < NCHUNK; c++) {
            const int s = s_cur;
            s_cur = (s_cur == 2) ? 0 : s_cur + 1;
            const uint32_t ncur = (s == 0) ? n0c : (s == 1) ? n1c : n2c;
            const uint32_t par = ncur & 1u;
            const uint32_t sa = base + (uint32_t)s * STAGE_BYTES;
            const uint32_t fb = full0 + (uint32_t)s * 8u;
            const uint32_t eb = empty0 + (uint32_t)s * 8u;

            if (wid == 0) {
                if (elect_one_pred()) {
                    MBARRIER_WAIT_PARITY(fb, par);     // lag<=1 per stage: alias-safe
                    const uint64_t ad0 = make_desc(sa);
                    const uint64_t ad1 = make_desc(sa + 16384u);
                    const uint64_t bd0 = make_desc(sa + 32768u);
                    const uint64_t bd1 = make_desc(sa + 49152u);
                    #pragma unroll
                    for (int ks = 0; ks < 4; ks++) {
                        const uint32_t acc = (c > 0 || ks > 0) ? 1u : 0u;
                        const uint64_t kadd = (uint64_t)(ks * 2);
                        mma_f16_ss(tmem + 0u,   ad0 + kadd, bd0 + kadd, GEMM_IDESC, acc);
                        mma_f16_ss(tmem + 128u, ad0 + kadd, bd1 + kadd, GEMM_IDESC, acc);
                        mma_f16_ss(tmem + 256u, ad1 + kadd, bd0 + kadd, GEMM_IDESC, acc);
                        mma_f16_ss(tmem + 384u, ad1 + kadd, bd1 + kadd, GEMM_IDESC, acc);
                    }
                    TCGEN05_COMMIT(eb);
                }
            } else if (wid == 1) {
                if (elect_one_pred()) {
                    // fill chunk c+3 (this tile, or next tile's chunk c+3-64)
                    int kx, ya, yb;
                    bool valid;
                    if (c + 3 < NCHUNK) {
                        valid = true; kx = (c + 3) * BK; ya = m0; yb = nn0;
                    } else if (tn < NTILES) {
                        valid = true; kx = (c + 3 - NCHUNK) * BK; ya = m0n; yb = nn0n;
                    } else {
                        valid = false; kx = 0; ya = 0; yb = 0;
                    }
                    if (valid) {
                        MBARRIER_WAIT_PARITY(eb, par);   // MMA(c) done reading stage s; lag<=1
                        MBARRIER_EXPECT_TX(fb, STAGE_TX);
                        TMA_LOAD_2D(sa,           &mapA, kx, ya, fb);
                        TMA_LOAD_2D(sa + 32768u,  &mapB, kx, yb, fb);
                    }
                }
            }
            if (s == 0) n0c++; else if (s == 1) n1c++; else n2c++;
        }

        // Tile-done barrier: ONE commit after all 64 chunks (MMA execution is
        // in-order, so this fires only after every MMA of this tile completes).
        // Alias-safe: all warps are in the same tile iteration (loop-top
        // __syncthreads), so completed phases at this wait are {tile_cnt-1, tile_cnt}.
        if (wid == 0 && elect_one_pred()) TCGEN05_COMMIT(doneb);
        MBARRIER_WAIT_PARITY(doneb, tile_cnt & 1u);
        tile_cnt++;
        TCGEN05_FENCE_AFTER();

        // Epilogue: direct coalesced stores; thread owns row m, 32 consecutive
        // cols (one 128B line) per block.
        {
            const int sp = wid & 3;
            const int dsel = wid >> 2;
            const int m = m0 + dsel * 128 + sp * 32 + lid;
            const uint32_t dbase = tmem + (uint32_t)(dsel * 256);
            float* orow = out + (size_t)m * N_DIM + nn0;

            for (int cc = 0; cc < BN; cc += 32) {
                uint32_t d[32];
                TCGEN05_LD_32X32B_X32(d, dbase + (uint32_t)cc);
                TCGEN05_WAIT_LD();
                const float4* b4 = reinterpret_cast<const float4*>(bias + nn0 + cc);
                float4* o4 = reinterpret_cast<float4*>(orow + cc);
                #pragma unroll
                for (int q = 0; q < 8; q++) {
                    float4 bv = __ldg(b4 + q);
                    float4 ov;
                    ov.x = __uint_as_float(d[q * 4 + 0]) + bv.x;
                    ov.y = __uint_as_float(d[q * 4 + 1]) + bv.y;
                    ov.z = __uint_as_float(d[q * 4 + 2]) + bv.z;
                    ov.w = __uint_as_float(d[q * 4 + 3]) + bv.w;
                    o4[q] = ov;
                }
            }
            TCGEN05_FENCE_BEFORE();
        }

        t = tn;
    }

    __syncthreads();
    if (wid == 0) {
        TCGEN05_RELINQUISH();
        TCGEN05_DEALLOC(tmem, 512);
    }

#else
    // ================= mma.sync fallback (baseline pass; not expected to run) ======
    __nv_bfloat16* fA = reinterpret_cast<__nv_bfloat16*>(smem_raw);   // [128][64]
    __nv_bfloat16* fB = fA + 128 * 64;                                 // [128][64]

    const int tt = blockIdx.x;
    const int m0 = (tt / NT_X) * BM;
    const int n0 = (tt % NT_X) * BN;

    const int wr = wid >> 1;
    const int wc = wid & 1;
    const int lq = lid >> 2;
    const int lr = (lid & 3) * 2;

    for (int sub = 0; sub < 4; sub++) {
        const int sm0 = m0 + (sub >> 1) * 128;
        const int sn0 = n0 + (sub & 1) * 128;

        float acc[16][4];
        #pragma unroll
        for (int i = 0; i < 16; i++)
            #pragma unroll
            for (int j = 0; j < 4; j++) acc[i][j] = 0.0f;

        for (int c = 0; c < NCHUNK; c++) {
            __syncthreads();
            #pragma unroll
            for (int j = 0; j < 4; j++) {
                int idx = j * GEMM_THREADS + tid;
                int row = idx >> 3;
                int seg = idx & 7;
                reinterpret_cast<uint4*>(fA)[row * 8 + seg] =
                    *(reinterpret_cast<const uint4*>(A + (size_t)(sm0 + row) * K_DIM + c * BK) + seg);
                reinterpret_cast<uint4*>(fB)[row * 8 + seg] =
                    *(reinterpret_cast<const uint4*>(B + (size_t)(sn0 + row) * K_DIM + c * BK) + seg);
            }
            __syncthreads();

            #pragma unroll
            for (int kk = 0; kk < 4; kk++) {
                const int kb = kk * 16;
                uint32_t afr[2][4];
                #pragma unroll
                for (int mt = 0; mt < 2; mt++) {
                    int ar = wr * 32 + mt * 16 + lq;
                    int ac = kb + lr;
                    afr[mt][0] = *reinterpret_cast<const uint32_t*>(fA + ar * 64 + ac);
                    afr[mt][1] = *reinterpret_cast<const uint32_t*>(fA + (ar + 8) * 64 + ac);
                    afr[mt][2] = *reinterpret_cast<const uint32_t*>(fA + ar * 64 + ac + 8);
                    afr[mt][3] = *reinterpret_cast<const uint32_t*>(fA + (ar + 8) * 64 + ac + 8);
                }
                uint32_t bfr[8][2];
                #pragma unroll
                for (int nt = 0; nt < 8; nt++) {
                    int bn = wc * 64 + nt * 8 + lq;
                    int bk = kb + lr;
                    bfr[nt][0] = *reinterpret_cast<const uint32_t*>(fB + bn * 64 + bk);
                    bfr[nt][1] = *reinterpret_cast<const uint32_t*>(fB + bn * 64 + bk + 8);
                }
                #pragma unroll
                for (int mt = 0; mt < 2; mt++)
                    #pragma unroll
                    for (int nt = 0; nt < 8; nt++) {
                        float* d = acc[mt * 8 + nt];
                        asm volatile(
                            "mma.sync.aligned.m16n8k16.row.col.f32.bf16.bf16.f32 "
                            "{%0,%1,%2,%3}, {%4,%5,%6,%7}, {%8,%9}, {%0,%1,%2,%3};"
                            : "+f"(d[0]), "+f"(d[1]), "+f"(d[2]), "+f"(d[3])
                            : "r"(afr[mt][0]), "r"(afr[mt][1]), "r"(afr[mt][2]), "r"(afr[mt][3]),
                              "r"(bfr[nt][0]), "r"(bfr[nt][1]));
                    }
            }
        }

        #pragma unroll
        for (int mt = 0; mt < 2; mt++) {
            #pragma unroll
            for (int nt = 0; nt < 8; nt++) {
                const float* d = acc[mt * 8 + nt];
                int r0 = sm0 + wr * 32 + mt * 16 + lq;
                int col = sn0 + wc * 64 + nt * 8 + lr;
                float b0 = __ldg(bias + col);
                float b1 = __ldg(bias + col + 1);
                out[(size_t)r0 * N_DIM + col]            = d[0] + b0;
                out[(size_t)r0 * N_DIM + col + 1]        = d[1] + b1;
                out[(size_t)(r0 + 8) * N_DIM + col]      = d[2] + b0;
                out[(size_t)(r0 + 8) * N_DIM + col + 1]  = d[3] + b1;
            }
        }
        __syncthreads();
    }
#endif
}

// ---------------- host: tensormap encode via driver entry point ----------------
typedef CUresult (*PFN_encodeTiled)(
    CUtensorMap*, CUtensorMapDataType, cuuint32_t, void*,
    const cuuint64_t*, const cuuint64_t*, const cuuint32_t*, const cuuint32_t*,
    CUtensorMapInterleave, CUtensorMapSwizzle, CUtensorMapL2promotion,
    CUtensorMapFloatOOBfill);

static void encode_map(CUtensorMap* map, void* ptr, uint64_t rows, uint64_t cols_k) {
    void* p = nullptr;
    cudaDriverEntryPointQueryResult st;
    cudaGetDriverEntryPointByVersion("cuTensorMapEncodeTiled", &p, 12000,
                                     cudaEnableDefault, &st);
    PFN_encodeTiled fn = (PFN_encodeTiled)p;
    cuuint64_t dims[2]    = {cols_k, rows};
    cuuint64_t strides[1] = {cols_k * 2};          // bytes per row
    cuuint32_t box[2]     = {BK, 256};
    cuuint32_t estr[2]    = {1, 1};
    fn(map, CU_TENSOR_MAP_DATA_TYPE_BFLOAT16, 2, ptr,
       dims, strides, box, estr,
       CU_TENSOR_MAP_INTERLEAVE_NONE, CU_TENSOR_MAP_SWIZZLE_128B,
       CU_TENSOR_MAP_L2_PROMOTION_L2_128B,
       CU_TENSOR_MAP_FLOAT_OOB_FILL_NONE);
}

// ---------------- launcher ----------------
extern "C" void kernel_launch(void* const* d_in, const int* in_sizes, int n_in,
                              void* d_out, int out_size) {
    (void)in_sizes; (void)n_in; (void)out_size;
    const float* x    = (const float*)d_in[0];   // [8192, 4096]
    const float* w    = (const float*)d_in[1];   // [4096, 4096]
    const float* bias = (const float*)d_in[2];   // [4096]
    float* out = (float*)d_out;                  // [8192, 4096]

    __nv_bfloat16 *xq = nullptr, *wq = nullptr;
    cudaGetSymbolAddress((void**)&xq, g_xq);
    cudaGetSymbolAddress((void**)&wq, g_wq);

    CUtensorMap mapA, mapB;
    encode_map(&mapA, xq, M_DIM, K_DIM);
    encode_map(&mapB, wq, N_DIM, K_DIM);

    const int xg = M_DIM * K_DIM / 16;
    const int wg = N_DIM * K_DIM / 16;
    dequant_kernel<<<xg / 256, 256>>>(x, xq, xg);
    dequant_kernel<<<wg / 256, 256>>>(w, wq, wg);

    reset_ctr_kernel<<<1, 1>>>();

    cudaFuncSetAttribute(gemm_fp4, cudaFuncAttributeMaxDynamicSharedMemorySize, GEMM_SMEM_BYTES);
    gemm_fp4<<<NTILES, GEMM_THREADS, GEMM_SMEM_BYTES>>>(mapA, mapB, xq, wq, bias, out);
}

// round 7
// speedup vs baseline: 2.5469x; 1.5153x over previous
#include <cuda_runtime.h>
#include <cuda.h>
#include <cuda_bf16.h>
#include <cuda_fp8.h>
#include <stdint.h>

#define M_DIM 8192
#define K_DIM 4096
#define N_DIM 4096
#define GPR (K_DIM / 16)   // 256 groups/row
#define GWR (K_DIM / 64)   // 64 SF words/row

#if defined(__CUDA_ARCH__) && (__CUDA_ARCH__ >= 1000) && \
    (defined(__CUDA_ARCH_FEAT_SM103_ALL) || defined(__CUDA_ARCH_FEAT_SM100_ALL) || \
     defined(__CUDA_ARCH_SPECIFIC__) || defined(__CUDA_ARCH_FAMILY_SPECIFIC__))
#define USE_TCGEN05 1
#else
#define USE_TCGEN05 0
#endif

// ---------------- scratch ----------------
__device__ uint64_t g_xq4[(size_t)M_DIM * GPR];   // packed e2m1 x, 16 MB
__device__ uint64_t g_wq4[(size_t)N_DIM * GPR];   // packed e2m1 w,  8 MB
__device__ uint32_t g_sfa[(size_t)GWR * M_DIM];   // SF words [gw][m]
__device__ uint32_t g_sfb[(size_t)GWR * N_DIM];   // SF words [gw][n]
__device__ unsigned int g_tile_ctr;
__constant__ float c_lut[8] = {0.f, 0.5f, 1.f, 1.5f, 2.f, 3.f, 4.f, 6.f};

__global__ void reset_ctr_kernel() { g_tile_ctr = 0u; }

__device__ __forceinline__ uint32_t smem_u32(const void* p) {
    uint32_t a;
    asm("{ .reg .u64 t; cvta.to.shared.u64 t, %1; cvt.u32.u64 %0, t; }" : "=r"(a) : "l"(p));
    return a;
}

#if USE_TCGEN05
__device__ __forceinline__ uint32_t elect_one_pred() {
    uint32_t pred;
    asm volatile("{\n\t.reg .pred p;\n\telect.sync _|p, 0xFFFFFFFF;\n\t"
                 "selp.b32 %0, 1, 0, p;\n\t}" : "=r"(pred));
    return pred;
}

#define MBARRIER_INIT(addr, cnt) \
    asm volatile("mbarrier.init.shared.b64 [%0], %1;" :: "r"((uint32_t)(addr)), "r"((uint32_t)(cnt)) : "memory")
#define MBARRIER_ARRIVE(addr) \
    asm volatile("mbarrier.arrive.shared.b64 _, [%0];" :: "r"((uint32_t)(addr)) : "memory")
#define MBARRIER_EXPECT_TX(addr, bytes) \
    asm volatile("mbarrier.arrive.expect_tx.shared.b64 _, [%0], %1;" \
        :: "r"((uint32_t)(addr)), "r"((uint32_t)(bytes)) : "memory")
#define MBARRIER_WAIT_PARITY(mbar_smem_addr, phase_parity) do { \
    uint32_t _mbar = (uint32_t)(mbar_smem_addr); \
    uint32_t _parity = (uint32_t)(phase_parity); \
    uint32_t _done; \
    asm volatile("{\n\t.reg .pred p;\n\t" \
        "mbarrier.try_wait.parity.acquire.cta.shared::cta.b64 p, [%1], %2;\n\t" \
        "selp.b32 %0, 1, 0, p;\n\t}" : "=r"(_done) : "r"(_mbar), "r"(_parity) : "memory"); \
    if (!_done) { \
        asm volatile("{\n\t.reg .pred P1;\n\t" \
            "WAIT_LOOP_%=:\n\t" \
            "mbarrier.try_wait.parity.acquire.cta.shared::cta.b64 P1, [%0], %1, 0x989680;\n\t" \
            "@P1 bra.uni WAIT_DONE_%=;\n\t" \
            "bra.uni WAIT_LOOP_%=;\n\t" \
            "WAIT_DONE_%=:\n\t}" :: "r"(_mbar), "r"(_parity) : "memory"); \
    } \
} while (0)

#define TMA_LOAD_2D(smem_addr, map_ptr, cx, cy, mbar) \
    asm volatile("cp.async.bulk.tensor.2d.shared::cta.global.tile.mbarrier::complete_tx::bytes " \
        "[%0], [%1, {%2, %3}], [%4];" \
        :: "r"((uint32_t)(smem_addr)), "l"(map_ptr), "r"((int)(cx)), "r"((int)(cy)), \
           "r"((uint32_t)(mbar)) : "memory")

#define TCGEN05_ALLOC(a, n) \
    asm volatile("tcgen05.alloc.cta_group::1.sync.aligned.shared::cta.b32 [%0], %1;" \
        :: "r"((uint32_t)(a)), "r"((uint32_t)(n)) : "memory")
#define TCGEN05_DEALLOC(t, n) \
    asm volatile("tcgen05.dealloc.cta_group::1.sync.aligned.b32 %0, %1;" :: "r"(t), "r"((uint32_t)(n)))
#define TCGEN05_RELINQUISH() \
    asm volatile("tcgen05.relinquish_alloc_permit.cta_group::1.sync.aligned;")
#define TCGEN05_COMMIT(m) \
    asm volatile("tcgen05.commit.cta_group::1.mbarrier::arrive::one.shared::cluster.b64 [%0];" \
        :: "r"((uint32_t)(m)) : "memory")
#define TCGEN05_WAIT_LD() asm volatile("tcgen05.wait::ld.sync.aligned;" ::: "memory")
#define TCGEN05_WAIT_ST() asm volatile("tcgen05.wait::st.sync.aligned;" ::: "memory")
#define TCGEN05_FENCE_AFTER()  asm volatile("tcgen05.fence::after_thread_sync;" ::: "memory")
#define TCGEN05_FENCE_BEFORE() asm volatile("tcgen05.fence::before_thread_sync;" ::: "memory")

#define TCGEN05_LD_32X32B_X32(r, tmem_addr) \
    asm volatile("tcgen05.ld.sync.aligned.32x32b.x32.b32 " \
        "{%0, %1, %2, %3, %4, %5, %6, %7, " \
        " %8, %9, %10, %11, %12, %13, %14, %15, " \
        " %16, %17, %18, %19, %20, %21, %22, %23, " \
        " %24, %25, %26, %27, %28, %29, %30, %31}, [%32];" \
        : "=r"((r)[0]),  "=r"((r)[1]),  "=r"((r)[2]),  "=r"((r)[3]), \
          "=r"((r)[4]),  "=r"((r)[5]),  "=r"((r)[6]),  "=r"((r)[7]), \
          "=r"((r)[8]),  "=r"((r)[9]),  "=r"((r)[10]), "=r"((r)[11]), \
          "=r"((r)[12]), "=r"((r)[13]), "=r"((r)[14]), "=r"((r)[15]), \
          "=r"((r)[16]), "=r"((r)[17]), "=r"((r)[18]), "=r"((r)[19]), \
          "=r"((r)[20]), "=r"((r)[21]), "=r"((r)[22]), "=r"((r)[23]), \
          "=r"((r)[24]), "=r"((r)[25]), "=r"((r)[26]), "=r"((r)[27]), \
          "=r"((r)[28]), "=r"((r)[29]), "=r"((r)[30]), "=r"((r)[31]) \
        : "r"(tmem_addr))

__device__ __forceinline__ void ttst4(uint32_t addr, uint32_t r0, uint32_t r1,
                                      uint32_t r2, uint32_t r3) {
    asm volatile("tcgen05.st.sync.aligned.32x32b.x4.b32 [%0], {%1, %2, %3, %4};"
        :: "r"(addr), "r"(r0), "r"(r1), "r"(r2), "r"(r3) : "memory");
}

__device__ __forceinline__ uint64_t make_desc(uint32_t addr) {
    const uint64_t base = (2ull << 61) | (1ull << 46) | (64ull << 32) | (1ull << 16);
    return base | ((uint64_t)(addr >> 4) & 0x3FFFull);
}

// nvf4: e2m1 data (SMEM SS), ue4m3 SF (TMEM), scale_vec::4X, fp32 accum.
__device__ __forceinline__ void mma_nvf4_ss(uint32_t d, uint64_t a_desc, uint64_t b_desc,
                                            uint32_t idesc, uint32_t sfa, uint32_t sfb,
                                            uint32_t acc) {
    asm volatile("{\n\t.reg .pred p;\n\tsetp.ne.u32 p, %6, 0;\n\t"
        "tcgen05.mma.cta_group::1.kind::mxf4nvf4.block_scale.scale_vec::4X "
        "[%0], %1, %2, %3, [%4], [%5], p;\n\t}"
        :: "r"(d), "l"(a_desc), "l"(b_desc), "r"(idesc), "r"(sfa), "r"(sfb), "r"(acc)
        : "memory");
}
#endif  // USE_TCGEN05

// ---------------- quant: fp32 -> packed e2m1 + e4m3 SF ----------------
// Division-free bucketing proven bit-exact vs reference (rel_err 0.0 in R5/R6).
__global__ void __launch_bounds__(256) quant_fp4_kernel(const float* __restrict__ in,
                                                        uint64_t* __restrict__ outq,
                                                        uint8_t* __restrict__ sfp,
                                                        int nrows, int ngroups) {
    int g = blockIdx.x * blockDim.x + threadIdx.x;
    if (g >= ngroups) return;

    const float4* p = reinterpret_cast<const float4*>(in) + (size_t)g * 4;
    float v[16];
    {
        float4 t0 = p[0], t1 = p[1], t2 = p[2], t3 = p[3];
        v[0]=t0.x; v[1]=t0.y; v[2]=t0.z;  v[3]=t0.w;
        v[4]=t1.x; v[5]=t1.y; v[6]=t1.z;  v[7]=t1.w;
        v[8]=t2.x; v[9]=t2.y; v[10]=t2.z; v[11]=t2.w;
        v[12]=t3.x; v[13]=t3.y; v[14]=t3.z; v[15]=t3.w;
    }
    float amax = 0.0f;
    #pragma unroll
    for (int i = 0; i < 16; i++) amax = fmaxf(amax, fabsf(v[i]));

    float sraw = __fdiv_rn(amax, 6.0f);
    __nv_fp8_e4m3 s8(sraw);
    float scale = float(s8);

    uint64_t pack = 0;
    if (scale > 0.0f) {
        const float t0 = 0.25f * scale, t1 = 0.75f * scale, t2 = 1.25f * scale,
                    t3 = 1.75f * scale, t4 = 2.5f * scale,  t5 = 3.5f * scale,
                    t6 = 5.0f * scale;
        #pragma unroll
        for (int i = 0; i < 16; i++) {
            float a = fabsf(v[i]);
            uint32_t code;
            if      (a < t0) code = 0u;
            else if (a < t1) code = 1u;
            else if (a < t2) code = 2u;
            else if (a < t3) code = 3u;
            else if (a < t4) code = 4u;
            else if (a < t5) code = 5u;
            else if (a < t6) code = 6u;
            else             code = 7u;
            if (v[i] < 0.0f) code |= 8u;
            pack |= (uint64_t)code << (4 * i);   // low nibble = lowest K
        }
    }
    outq[g] = pack;

    int m = g / GPR;
    int G = g % GPR;
    sfp[(((size_t)(G >> 2)) * (size_t)nrows + (size_t)m) * 4 + (size_t)(G & 3)] =
        (scale > 0.0f || true) ? s8.__x : 0;   // byte j = group 4*gw+j
}

// ---------------- GEMM ----------------
#define BM 128
#define BN 256
#define GEMM_THREADS 256
#define NCHUNK 16                       // K / 256
#define NT_X (N_DIM / BN)               // 16
#define NTILES ((M_DIM / BM) * NT_X)    // 1024
#define NSTAGE 4
#define A_BYTES (BM * 128)              // 16384
#define STAGE_BYTES 49152               // A 16K + B 32K
#define STAGE_TX 49152
#define TMEM_SF 256
#define SF_COLS 48
// idesc: atype=btype=E2M1(1) @[7:9]/[10:12], N=128 -> 16 @[17:22],
// UE4M3 (bit23=0), M=128 -> 1 @[27:28], SFA_ID/SFB_ID = 0.
#define GEMM_IDESC ((1u << 7) | (1u << 10) | (16u << 17) | (1u << 27))
#define HDR_OFF (NSTAGE * STAGE_BYTES)
#define GEMM_SMEM_BYTES (HDR_OFF + 128 + 1024)

#if USE_TCGEN05
// Warps 4-7: fill SF TMEM stage s for chunk kc of tile (m0,n0). Replicated layout
// (HW-verified in examples): SFA col holds rows c*32+lid; SFB replicated per subpart.
__device__ __forceinline__ void sf_fill(uint32_t tmem, int s, int kc, int m0, int n0,
                                        int lid, uint32_t warp_off) {
    const uint32_t sfbase = tmem + TMEM_SF + (uint32_t)s * SF_COLS;
    #pragma unroll
    for (int ks = 0; ks < 4; ks++) {
        const size_t gw = (size_t)(kc * 4 + ks);
        const uint32_t* __restrict__ pa = g_sfa + gw * M_DIM + m0 + lid;
        ttst4(sfbase + (uint32_t)(ks * 4) + warp_off,
              __ldg(pa), __ldg(pa + 32), __ldg(pa + 64), __ldg(pa + 96));
        const uint32_t* __restrict__ pb = g_sfb + gw * N_DIM + n0 + lid;
        ttst4(sfbase + 16u + (uint32_t)(ks * 8) + warp_off,
              __ldg(pb), __ldg(pb + 32), __ldg(pb + 64), __ldg(pb + 96));
        ttst4(sfbase + 16u + (uint32_t)(ks * 8) + 4u + warp_off,
              __ldg(pb + 128), __ldg(pb + 160), __ldg(pb + 192), __ldg(pb + 224));
    }
    TCGEN05_WAIT_ST();
}
#endif

__global__ void __launch_bounds__(GEMM_THREADS, 1)
gemm_fp4(const __grid_constant__ CUtensorMap mapA,
         const __grid_constant__ CUtensorMap mapB,
         const float* __restrict__ bias,
         float* __restrict__ out)
{
    extern __shared__ char smem_raw[];
    const int tid = threadIdx.x;
    const int wid = tid >> 5;
    const int lid = tid & 31;

#if USE_TCGEN05
    const uint32_t base = (smem_u32(smem_raw) + 1023u) & ~1023u;
    const uint32_t hdr = base + HDR_OFF;
    const uint32_t tmem_ptr_addr = hdr;
    const uint32_t full0    = hdr + 16u;
    const uint32_t empty0   = hdr + 48u;
    const uint32_t sf_full0 = hdr + 80u;
    const uint32_t doneb    = hdr + 112u;
    const uint32_t slot     = hdr + 120u;

    if (wid == 0) TCGEN05_ALLOC(tmem_ptr_addr, 512);
    if (tid == 0) {
        #pragma unroll
        for (int s = 0; s < NSTAGE; s++) {
            MBARRIER_INIT(full0    + (uint32_t)s * 8u, 1);
            MBARRIER_INIT(empty0   + (uint32_t)s * 8u, 1);
            MBARRIER_INIT(sf_full0 + (uint32_t)s * 8u, 4);   // 4 SF warps
        }
        MBARRIER_INIT(doneb, 1);
        unsigned int t0 = atomicAdd(&g_tile_ctr, 1u);
        asm volatile("st.shared.u32 [%0], %1;" :: "r"(slot), "r"(t0) : "memory");
    }
    __syncthreads();

    uint32_t tmem;
    asm volatile("ld.shared.b32 %0, [%1];" : "=r"(tmem) : "r"(tmem_ptr_addr));
    uint32_t t;
    asm volatile("ld.shared.u32 %0, [%1];" : "=r"(t) : "r"(slot));

    const uint32_t warp_off = (uint32_t)(wid & 3) << 21;
    uint32_t gc = 0;          // s = gc&3, parity = (gc>>2)&1
    uint32_t tile_cnt = 0;
    bool first = true;

    while (t < NTILES) {
        if (tid == 0) {
            unsigned int tn_ = atomicAdd(&g_tile_ctr, 1u);
            asm volatile("st.shared.u32 [%0], %1;" :: "r"(slot), "r"(tn_) : "memory");
        }
        __syncthreads();
        uint32_t tn;
        asm volatile("ld.shared.u32 %0, [%1];" : "=r"(tn) : "r"(slot));

        const int m0  = (int)(t / NT_X) * BM;
        const int n0  = (int)(t % NT_X) * BN;
        const int m0n = (int)(tn / NT_X) * BM;    // valid only if tn < NTILES
        const int n0n = (int)(tn % NT_X) * BN;

        if (first) {
            if (wid == 1 && elect_one_pred()) {
                #pragma unroll
                for (int p = 0; p < NSTAGE; p++) {
                    const uint32_t fb = full0 + (uint32_t)p * 8u;
                    MBARRIER_EXPECT_TX(fb, STAGE_TX);
                    TMA_LOAD_2D(base + (uint32_t)p * STAGE_BYTES,           &mapA, p * 128, m0, fb);
                    TMA_LOAD_2D(base + (uint32_t)p * STAGE_BYTES + A_BYTES, &mapB, p * 128, n0, fb);
                }
            } else if (wid >= 4) {
                #pragma unroll
                for (int p = 0; p < NSTAGE; p++) {
                    sf_fill(tmem, p, p, m0, n0, lid, warp_off);
                    TCGEN05_FENCE_BEFORE();
                    if (lid == 0) MBARRIER_ARRIVE(sf_full0 + (uint32_t)p * 8u);
                }
            }
            first = false;
        }

        for (int c = 0; c < NCHUNK; c++, gc++) {
            const int s = (int)(gc & 3u);
            const uint32_t par = (gc >> 2) & 1u;
            const uint32_t sa = base + (uint32_t)s * STAGE_BYTES;

            if (wid == 0) {
                if (elect_one_pred()) {
                    MBARRIER_WAIT_PARITY(full0    + (uint32_t)s * 8u, par);
                    MBARRIER_WAIT_PARITY(sf_full0 + (uint32_t)s * 8u, par);
                    TCGEN05_FENCE_AFTER();
                    const uint64_t ad  = make_desc(sa);
                    const uint64_t bd0 = make_desc(sa + 16384u);
                    const uint64_t bd1 = make_desc(sa + 32768u);
                    const uint32_t sfbase = tmem + TMEM_SF + (uint32_t)s * SF_COLS;
                    #pragma unroll
                    for (int ks = 0; ks < 4; ks++) {
                        const uint32_t acc = (c > 0 || ks > 0) ? 1u : 0u;
                        const uint64_t ka = (uint64_t)(ks * 2);     // +32B = K 64 e2m1
                        const uint32_t sfa  = sfbase + (uint32_t)(ks * 4);
                        const uint32_t sfb0 = sfbase + 16u + (uint32_t)(ks * 8);
                        mma_nvf4_ss(tmem + 0u,   ad + ka, bd0 + ka, GEMM_IDESC, sfa, sfb0,      acc);
                        mma_nvf4_ss(tmem + 128u, ad + ka, bd1 + ka, GEMM_IDESC, sfa, sfb0 + 4u, acc);
                    }
                    TCGEN05_COMMIT(empty0 + (uint32_t)s * 8u);
                }
            } else if (wid == 1) {
                if (elect_one_pred()) {
                    int cc = c + NSTAGE, kx, ya, yb;
                    bool valid;
                    if (cc < NCHUNK)      { valid = true;  kx = cc * 128;            ya = m0;  yb = n0;  }
                    else if (tn < NTILES) { valid = true;  kx = (cc - NCHUNK) * 128; ya = m0n; yb = n0n; }
                    else                  { valid = false; kx = 0; ya = 0; yb = 0; }
                    if (valid) {
                        MBARRIER_WAIT_PARITY(empty0 + (uint32_t)s * 8u, par);
                        MBARRIER_EXPECT_TX(full0 + (uint32_t)s * 8u, STAGE_TX);
                        TMA_LOAD_2D(sa,           &mapA, kx, ya, full0 + (uint32_t)s * 8u);
                        TMA_LOAD_2D(sa + A_BYTES, &mapB, kx, yb, full0 + (uint32_t)s * 8u);
                    }
                }
            } else if (wid >= 4) {
                int cc = c + NSTAGE, kc, ya, yb;
                bool valid;
                if (cc < NCHUNK)      { valid = true;  kc = cc;          ya = m0;  yb = n0;  }
                else if (tn < NTILES) { valid = true;  kc = cc - NCHUNK; ya = m0n; yb = n0n; }
                else                  { valid = false; kc = 0; ya = 0; yb = 0; }
                if (valid) {
                    MBARRIER_WAIT_PARITY(empty0 + (uint32_t)s * 8u, par);
                    sf_fill(tmem, s, kc, ya, yb, lid, warp_off);
                    TCGEN05_FENCE_BEFORE();
                    if (lid == 0) MBARRIER_ARRIVE(sf_full0 + (uint32_t)s * 8u);
                }
            }
        }

        // Tile-done: one commit after all chunks (in-order MMA). Alias-safe per R5.
        if (wid == 0 && elect_one_pred()) TCGEN05_COMMIT(doneb);
        MBARRIER_WAIT_PARITY(doneb, tile_cnt & 1u);
        tile_cnt++;
        TCGEN05_FENCE_AFTER();

        // Epilogue: warp w -> rows m0+(w&3)*32+lid, cols (w>>2)*128..+127.
        {
            const int m = m0 + (wid & 3) * 32 + lid;
            const int nb = n0 + (wid >> 2) * 128;
            const uint32_t dbase = tmem + (uint32_t)((wid >> 2) * 128);
            float* orow = out + (size_t)m * N_DIM + nb;
            for (int cc = 0; cc < 128; cc += 32) {
                uint32_t d[32];
                TCGEN05_LD_32X32B_X32(d, dbase + (uint32_t)cc);
                TCGEN05_WAIT_LD();
                const float4* b4 = reinterpret_cast<const float4*>(bias + nb + cc);
                float4* o4 = reinterpret_cast<float4*>(orow + cc);
                #pragma unroll
                for (int q = 0; q < 8; q++) {
                    float4 bv = __ldg(b4 + q);
                    float4 ov;
                    ov.x = __uint_as_float(d[q * 4 + 0]) + bv.x;
                    ov.y = __uint_as_float(d[q * 4 + 1]) + bv.y;
                    ov.z = __uint_as_float(d[q * 4 + 2]) + bv.z;
                    ov.w = __uint_as_float(d[q * 4 + 3]) + bv.w;
                    o4[q] = ov;
                }
            }
            TCGEN05_FENCE_BEFORE();
        }

        t = tn;
    }

    __syncthreads();
    if (wid == 0) {
        TCGEN05_RELINQUISH();
        TCGEN05_DEALLOC(tmem, 512);
    }

#else
    // ------- baseline-pass fallback: correct SIMT decode GEMM (never selected;
    // arch-specific SASS has been chosen by the driver in all prior rounds) -------
    const int tt = blockIdx.x;
    const int m0 = (tt / NT_X) * BM;
    const int n0 = (tt % NT_X) * BN;
    for (int idx = tid; idx < BM * BN; idx += GEMM_THREADS) {
        const int m = m0 + idx / BN;
        const int n = n0 + idx % BN;
        float acc = 0.0f;
        for (int G = 0; G < GPR; G++) {
            uint64_t av = g_xq4[(size_t)m * GPR + G];
            uint64_t bv = g_wq4[(size_t)n * GPR + G];
            __nv_fp8_e4m3 sa8, sb8;
            sa8.__x = (uint8_t)(g_sfa[(size_t)(G >> 2) * M_DIM + m] >> ((G & 3) * 8));
            sb8.__x = (uint8_t)(g_sfb[(size_t)(G >> 2) * N_DIM + n] >> ((G & 3) * 8));
            float fs = float(sa8) * float(sb8);
            float sum = 0.0f;
            #pragma unroll
            for (int i = 0; i < 16; i++) {
                uint32_t ca = (uint32_t)(av >> (4 * i)) & 15u;
                uint32_t cb = (uint32_t)(bv >> (4 * i)) & 15u;
                float va = c_lut[ca & 7u]; if (ca & 8u) va = -va;
                float vb = c_lut[cb & 7u]; if (cb & 8u) vb = -vb;
                sum += va * vb;
            }
            acc += sum * fs;
        }
        out[(size_t)m * N_DIM + n] = acc + __ldg(bias + n);
    }
#endif
}

// ---------------- host: tensormap encode ----------------
typedef CUresult (*PFN_encodeTiled)(
    CUtensorMap*, CUtensorMapDataType, cuuint32_t, void*,
    const cuuint64_t*, const cuuint64_t*, const cuuint32_t*, const cuuint32_t*,
    CUtensorMapInterleave, CUtensorMapSwizzle, CUtensorMapL2promotion,
    CUtensorMapFloatOOBfill);

static void encode_map_u8(CUtensorMap* map, void* ptr, uint64_t rows,
                          uint64_t row_bytes, uint32_t box_rows) {
    void* p = nullptr;
    cudaDriverEntryPointQueryResult st;
    cudaGetDriverEntryPointByVersion("cuTensorMapEncodeTiled", &p, 12000,
                                     cudaEnableDefault, &st);
    PFN_encodeTiled fn = (PFN_encodeTiled)p;
    cuuint64_t dims[2]    = {row_bytes, rows};
    cuuint64_t strides[1] = {row_bytes};
    cuuint32_t box[2]     = {128, box_rows};
    cuuint32_t estr[2]    = {1, 1};
    fn(map, CU_TENSOR_MAP_DATA_TYPE_UINT8, 2, ptr,
       dims, strides, box, estr,
       CU_TENSOR_MAP_INTERLEAVE_NONE, CU_TENSOR_MAP_SWIZZLE_128B,
       CU_TENSOR_MAP_L2_PROMOTION_L2_128B,
       CU_TENSOR_MAP_FLOAT_OOB_FILL_NONE);
}

// ---------------- launcher ----------------
extern "C" void kernel_launch(void* const* d_in, const int* in_sizes, int n_in,
                              void* d_out, int out_size) {
    (void)in_sizes; (void)n_in; (void)out_size;
    const float* x    = (const float*)d_in[0];
    const float* w    = (const float*)d_in[1];
    const float* bias = (const float*)d_in[2];
    float* out = (float*)d_out;

    uint64_t *xq4 = nullptr, *wq4 = nullptr;
    uint32_t *sfa = nullptr, *sfb = nullptr;
    cudaGetSymbolAddress((void**)&xq4, g_xq4);
    cudaGetSymbolAddress((void**)&wq4, g_wq4);
    cudaGetSymbolAddress((void**)&sfa, g_sfa);
    cudaGetSymbolAddress((void**)&sfb, g_sfb);

    CUtensorMap mapA, mapB;
    encode_map_u8(&mapA, xq4, M_DIM, K_DIM / 2, 128);   // A: [8192][2048B], box 128x128
    encode_map_u8(&mapB, wq4, N_DIM, K_DIM / 2, 256);   // B: [4096][2048B], box 128x256

    const int xg = M_DIM * GPR;
    const int wg = N_DIM * GPR;
    quant_fp4_kernel<<<xg / 256, 256>>>(x, xq4, (uint8_t*)sfa, M_DIM, xg);
    quant_fp4_kernel<<<wg / 256, 256>>>(w, wq4, (uint8_t*)sfb, N_DIM, wg);

    reset_ctr_kernel<<<1, 1>>>();

    cudaFuncSetAttribute(gemm_fp4, cudaFuncAttributeMaxDynamicSharedMemorySize, GEMM_SMEM_BYTES);
    gemm_fp4<<<NTILES, GEMM_THREADS, GEMM_SMEM_BYTES>>>(mapA, mapB, bias, out);
}

// round 8
// speedup vs baseline: 2.9353x; 1.1525x over previous
#include <cuda_runtime.h>
#include <cuda.h>
#include <cuda_bf16.h>
#include <cuda_fp8.h>
#include <stdint.h>

#define M_DIM 8192
#define K_DIM 4096
#define N_DIM 4096
#define GPR (K_DIM / 16)   // 256 groups/row
#define GWR (K_DIM / 64)   // 64 SF words/row

#if defined(__CUDA_ARCH__) && (__CUDA_ARCH__ >= 1000) && \
    (defined(__CUDA_ARCH_FEAT_SM103_ALL) || defined(__CUDA_ARCH_FEAT_SM100_ALL) || \
     defined(__CUDA_ARCH_SPECIFIC__) || defined(__CUDA_ARCH_FAMILY_SPECIFIC__))
#define USE_TCGEN05 1
#else
#define USE_TCGEN05 0
#endif

// ---------------- scratch ----------------
__device__ uint64_t g_xq4[(size_t)M_DIM * GPR];   // packed e2m1 x, 16 MB
__device__ uint64_t g_wq4[(size_t)N_DIM * GPR];   // packed e2m1 w,  8 MB
__device__ uint32_t g_sfa[(size_t)GWR * M_DIM];   // SF words [gw][m]
__device__ uint32_t g_sfb[(size_t)GWR * N_DIM];   // SF words [gw][n]
__device__ unsigned int g_tile_ctr;
__constant__ float c_lut[8] = {0.f, 0.5f, 1.f, 1.5f, 2.f, 3.f, 4.f, 6.f};

__global__ void reset_ctr_kernel() { g_tile_ctr = 0u; }

__device__ __forceinline__ uint32_t smem_u32(const void* p) {
    uint32_t a;
    asm("{ .reg .u64 t; cvta.to.shared.u64 t, %1; cvt.u32.u64 %0, t; }" : "=r"(a) : "l"(p));
    return a;
}

#if USE_TCGEN05
__device__ __forceinline__ uint32_t elect_one_pred() {
    uint32_t pred;
    asm volatile("{\n\t.reg .pred p;\n\telect.sync _|p, 0xFFFFFFFF;\n\t"
                 "selp.b32 %0, 1, 0, p;\n\t}" : "=r"(pred));
    return pred;
}

#define MBARRIER_INIT(addr, cnt) \
    asm volatile("mbarrier.init.shared.b64 [%0], %1;" :: "r"((uint32_t)(addr)), "r"((uint32_t)(cnt)) : "memory")
#define MBARRIER_ARRIVE(addr) \
    asm volatile("mbarrier.arrive.shared.b64 _, [%0];" :: "r"((uint32_t)(addr)) : "memory")
#define MBARRIER_EXPECT_TX(addr, bytes) \
    asm volatile("mbarrier.arrive.expect_tx.shared.b64 _, [%0], %1;" \
        :: "r"((uint32_t)(addr)), "r"((uint32_t)(bytes)) : "memory")
#define MBARRIER_WAIT_PARITY(mbar_smem_addr, phase_parity) do { \
    uint32_t _mbar = (uint32_t)(mbar_smem_addr); \
    uint32_t _parity = (uint32_t)(phase_parity); \
    uint32_t _done; \
    asm volatile("{\n\t.reg .pred p;\n\t" \
        "mbarrier.try_wait.parity.acquire.cta.shared::cta.b64 p, [%1], %2;\n\t" \
        "selp.b32 %0, 1, 0, p;\n\t}" : "=r"(_done) : "r"(_mbar), "r"(_parity) : "memory"); \
    if (!_done) { \
        asm volatile("{\n\t.reg .pred P1;\n\t" \
            "WAIT_LOOP_%=:\n\t" \
            "mbarrier.try_wait.parity.acquire.cta.shared::cta.b64 P1, [%0], %1, 0x989680;\n\t" \
            "@P1 bra.uni WAIT_DONE_%=;\n\t" \
            "bra.uni WAIT_LOOP_%=;\n\t" \
            "WAIT_DONE_%=:\n\t}" :: "r"(_mbar), "r"(_parity) : "memory"); \
    } \
} while (0)

#define TMA_LOAD_2D(smem_addr, map_ptr, cx, cy, mbar) \
    asm volatile("cp.async.bulk.tensor.2d.shared::cta.global.tile.mbarrier::complete_tx::bytes " \
        "[%0], [%1, {%2, %3}], [%4];" \
        :: "r"((uint32_t)(smem_addr)), "l"(map_ptr), "r"((int)(cx)), "r"((int)(cy)), \
           "r"((uint32_t)(mbar)) : "memory")

#define TCGEN05_ALLOC(a, n) \
    asm volatile("tcgen05.alloc.cta_group::1.sync.aligned.shared::cta.b32 [%0], %1;" \
        :: "r"((uint32_t)(a)), "r"((uint32_t)(n)) : "memory")
#define TCGEN05_DEALLOC(t, n) \
    asm volatile("tcgen05.dealloc.cta_group::1.sync.aligned.b32 %0, %1;" :: "r"(t), "r"((uint32_t)(n)))
#define TCGEN05_RELINQUISH() \
    asm volatile("tcgen05.relinquish_alloc_permit.cta_group::1.sync.aligned;")
#define TCGEN05_COMMIT(m) \
    asm volatile("tcgen05.commit.cta_group::1.mbarrier::arrive::one.shared::cluster.b64 [%0];" \
        :: "r"((uint32_t)(m)) : "memory")
#define TCGEN05_WAIT_LD() asm volatile("tcgen05.wait::ld.sync.aligned;" ::: "memory")
#define TCGEN05_WAIT_ST() asm volatile("tcgen05.wait::st.sync.aligned;" ::: "memory")
#define TCGEN05_FENCE_AFTER()  asm volatile("tcgen05.fence::after_thread_sync;" ::: "memory")
#define TCGEN05_FENCE_BEFORE() asm volatile("tcgen05.fence::before_thread_sync;" ::: "memory")

#define LDS32(r, addr) \
    asm volatile("ld.shared.b32 %0, [%1];" : "=r"(r) : "r"((uint32_t)(addr)))

#define TCGEN05_LD_32X32B_X32(r, tmem_addr) \
    asm volatile("tcgen05.ld.sync.aligned.32x32b.x32.b32 " \
        "{%0, %1, %2, %3, %4, %5, %6, %7, " \
        " %8, %9, %10, %11, %12, %13, %14, %15, " \
        " %16, %17, %18, %19, %20, %21, %22, %23, " \
        " %24, %25, %26, %27, %28, %29, %30, %31}, [%32];" \
        : "=r"((r)[0]),  "=r"((r)[1]),  "=r"((r)[2]),  "=r"((r)[3]), \
          "=r"((r)[4]),  "=r"((r)[5]),  "=r"((r)[6]),  "=r"((r)[7]), \
          "=r"((r)[8]),  "=r"((r)[9]),  "=r"((r)[10]), "=r"((r)[11]), \
          "=r"((r)[12]), "=r"((r)[13]), "=r"((r)[14]), "=r"((r)[15]), \
          "=r"((r)[16]), "=r"((r)[17]), "=r"((r)[18]), "=r"((r)[19]), \
          "=r"((r)[20]), "=r"((r)[21]), "=r"((r)[22]), "=r"((r)[23]), \
          "=r"((r)[24]), "=r"((r)[25]), "=r"((r)[26]), "=r"((r)[27]), \
          "=r"((r)[28]), "=r"((r)[29]), "=r"((r)[30]), "=r"((r)[31]) \
        : "r"(tmem_addr))

__device__ __forceinline__ void ttst4(uint32_t addr, uint32_t r0, uint32_t r1,
                                      uint32_t r2, uint32_t r3) {
    asm volatile("tcgen05.st.sync.aligned.32x32b.x4.b32 [%0], {%1, %2, %3, %4};"
        :: "r"(addr), "r"(r0), "r"(r1), "r"(r2), "r"(r3) : "memory");
}

__device__ __forceinline__ uint64_t make_desc(uint32_t addr) {
    const uint64_t base = (2ull << 61) | (1ull << 46) | (64ull << 32) | (1ull << 16);
    return base | ((uint64_t)(addr >> 4) & 0x3FFFull);
}

// nvf4: e2m1 data (SMEM SS), ue4m3 SF (TMEM), scale_vec::4X, fp32 accum.
__device__ __forceinline__ void mma_nvf4_ss(uint32_t d, uint64_t a_desc, uint64_t b_desc,
                                            uint32_t idesc, uint32_t sfa, uint32_t sfb,
                                            uint32_t acc) {
    asm volatile("{\n\t.reg .pred p;\n\tsetp.ne.u32 p, %6, 0;\n\t"
        "tcgen05.mma.cta_group::1.kind::mxf4nvf4.block_scale.scale_vec::4X "
        "[%0], %1, %2, %3, [%4], [%5], p;\n\t}"
        :: "r"(d), "l"(a_desc), "l"(b_desc), "r"(idesc), "r"(sfa), "r"(sfb), "r"(acc)
        : "memory");
}
#endif  // USE_TCGEN05

// ---------------- quant: fp32 -> packed e2m1 + e4m3 SF (bit-exact, proven) ----
__global__ void __launch_bounds__(256) quant_fp4_kernel(const float* __restrict__ in,
                                                        uint64_t* __restrict__ outq,
                                                        uint8_t* __restrict__ sfp,
                                                        int nrows, int ngroups) {
    int g = blockIdx.x * blockDim.x + threadIdx.x;
    if (g >= ngroups) return;

    const float4* p = reinterpret_cast<const float4*>(in) + (size_t)g * 4;
    float v[16];
    {
        float4 t0 = p[0], t1 = p[1], t2 = p[2], t3 = p[3];
        v[0]=t0.x; v[1]=t0.y; v[2]=t0.z;  v[3]=t0.w;
        v[4]=t1.x; v[5]=t1.y; v[6]=t1.z;  v[7]=t1.w;
        v[8]=t2.x; v[9]=t2.y; v[10]=t2.z; v[11]=t2.w;
        v[12]=t3.x; v[13]=t3.y; v[14]=t3.z; v[15]=t3.w;
    }
    float amax = 0.0f;
    #pragma unroll
    for (int i = 0; i < 16; i++) amax = fmaxf(amax, fabsf(v[i]));

    float sraw = __fdiv_rn(amax, 6.0f);
    __nv_fp8_e4m3 s8(sraw);
    float scale = float(s8);

    uint64_t pack = 0;
    if (scale > 0.0f) {
        const float t0 = 0.25f * scale, t1 = 0.75f * scale, t2 = 1.25f * scale,
                    t3 = 1.75f * scale, t4 = 2.5f * scale,  t5 = 3.5f * scale,
                    t6 = 5.0f * scale;
        #pragma unroll
        for (int i = 0; i < 16; i++) {
            float a = fabsf(v[i]);
            uint32_t code;
            if      (a < t0) code = 0u;
            else if (a < t1) code = 1u;
            else if (a < t2) code = 2u;
            else if (a < t3) code = 3u;
            else if (a < t4) code = 4u;
            else if (a < t5) code = 5u;
            else if (a < t6) code = 6u;
            else             code = 7u;
            if (v[i] < 0.0f) code |= 8u;
            pack |= (uint64_t)code << (4 * i);
        }
    }
    outq[g] = pack;

    int m = g / GPR;
    int G = g % GPR;
    sfp[(((size_t)(G >> 2)) * (size_t)nrows + (size_t)m) * 4 + (size_t)(G & 3)] = s8.__x;
}

// ---------------- GEMM ----------------
#define BM 128
#define BN 256
#define GEMM_THREADS 256
#define NCHUNK 16
#define NT_X (N_DIM / BN)               // 16
#define NTILES ((M_DIM / BM) * NT_X)    // 1024
#define NSTAGE 4
#define A_BYTES 16384
#define B_BYTES 32768
#define SFA_OFF (A_BYTES + B_BYTES)     // 49152
#define SFB_OFF (SFA_OFF + 2048)        // 51200
#define STAGE_BYTES 55296               // A + B + SFA(2K) + SFB(4K), 54*1024
#define STAGE_TX 55296
#define TMEM_SF 256
#define SF_COLS 48
#define GEMM_IDESC ((1u << 7) | (1u << 10) | (16u << 17) | (1u << 27))
#define HDR_OFF (NSTAGE * STAGE_BYTES)  // 221184
#define GEMM_SMEM_BYTES (HDR_OFF + 128 + 1024)

#if USE_TCGEN05
// SF warps: SMEM slab -> TMEM (layout byte-identical to the proven R7 one).
__device__ __forceinline__ void sf_fill_smem(uint32_t tmem, int s, uint32_t sa,
                                             int lid, uint32_t warp_off) {
    const uint32_t sfbase = tmem + TMEM_SF + (uint32_t)s * SF_COLS;
    const uint32_t pA = sa + SFA_OFF;
    const uint32_t pB = sa + SFB_OFF;
    #pragma unroll
    for (int ks = 0; ks < 4; ks++) {
        uint32_t a0, a1, a2, a3;
        LDS32(a0, pA + (uint32_t)(ks * 128 +   0 + lid) * 4u);
        LDS32(a1, pA + (uint32_t)(ks * 128 +  32 + lid) * 4u);
        LDS32(a2, pA + (uint32_t)(ks * 128 +  64 + lid) * 4u);
        LDS32(a3, pA + (uint32_t)(ks * 128 +  96 + lid) * 4u);
        ttst4(sfbase + (uint32_t)(ks * 4) + warp_off, a0, a1, a2, a3);
        uint32_t b[8];
        #pragma unroll
        for (int j = 0; j < 8; j++)
            LDS32(b[j], pB + (uint32_t)(ks * 256 + j * 32 + lid) * 4u);
        ttst4(sfbase + 16u + (uint32_t)(ks * 8) + warp_off,      b[0], b[1], b[2], b[3]);
        ttst4(sfbase + 16u + (uint32_t)(ks * 8) + 4u + warp_off, b[4], b[5], b[6], b[7]);
    }
    TCGEN05_WAIT_ST();
}
#endif

__global__ void __launch_bounds__(GEMM_THREADS, 1)
gemm_fp4(const __grid_constant__ CUtensorMap mapA,
         const __grid_constant__ CUtensorMap mapB,
         const __grid_constant__ CUtensorMap mapSA,
         const __grid_constant__ CUtensorMap mapSB,
         const float* __restrict__ bias,
         float* __restrict__ out)
{
    extern __shared__ char smem_raw[];
    const int tid = threadIdx.x;
    const int wid = tid >> 5;
    const int lid = tid & 31;

#if USE_TCGEN05
    const uint32_t base = (smem_u32(smem_raw) + 1023u) & ~1023u;
    const uint32_t hdr = base + HDR_OFF;
    const uint32_t tmem_ptr_addr = hdr;
    const uint32_t full0    = hdr + 16u;
    const uint32_t empty0   = hdr + 48u;
    const uint32_t sf_full0 = hdr + 80u;
    const uint32_t doneb    = hdr + 112u;
    const uint32_t slot     = hdr + 120u;

    if (wid == 0) TCGEN05_ALLOC(tmem_ptr_addr, 512);
    if (tid == 0) {
        #pragma unroll
        for (int s = 0; s < NSTAGE; s++) {
            MBARRIER_INIT(full0    + (uint32_t)s * 8u, 1);
            MBARRIER_INIT(empty0   + (uint32_t)s * 8u, 1);
            MBARRIER_INIT(sf_full0 + (uint32_t)s * 8u, 4);
        }
        MBARRIER_INIT(doneb, 1);
        unsigned int t0 = atomicAdd(&g_tile_ctr, 1u);
        asm volatile("st.shared.u32 [%0], %1;" :: "r"(slot), "r"(t0) : "memory");
    }
    __syncthreads();

    uint32_t tmem;
    asm volatile("ld.shared.b32 %0, [%1];" : "=r"(tmem) : "r"(tmem_ptr_addr));
    uint32_t t;
    asm volatile("ld.shared.u32 %0, [%1];" : "=r"(t) : "r"(slot));

    const uint32_t warp_off = (uint32_t)(wid & 3) << 21;
    uint32_t gc = 0;          // s = gc&3, parity = (gc>>2)&1
    uint32_t tile_cnt = 0;
    bool first = true;

    while (t < NTILES) {
        if (tid == 0) {
            unsigned int tn_ = atomicAdd(&g_tile_ctr, 1u);
            asm volatile("st.shared.u32 [%0], %1;" :: "r"(slot), "r"(tn_) : "memory");
        }
        __syncthreads();
        uint32_t tn;
        asm volatile("ld.shared.u32 %0, [%1];" : "=r"(tn) : "r"(slot));

        const int m0  = (int)(t / NT_X) * BM;
        const int n0  = (int)(t % NT_X) * BN;
        const int m0n = (int)(tn / NT_X) * BM;    // valid only if tn < NTILES
        const int n0n = (int)(tn % NT_X) * BN;

        if (first) {
            if (wid == 1 && elect_one_pred()) {
                #pragma unroll
                for (int p = 0; p < NSTAGE; p++) {
                    const uint32_t fb = full0 + (uint32_t)p * 8u;
                    const uint32_t sa = base + (uint32_t)p * STAGE_BYTES;
                    MBARRIER_EXPECT_TX(fb, STAGE_TX);
                    TMA_LOAD_2D(sa,           &mapA,  p * 128, m0,    fb);
                    TMA_LOAD_2D(sa + A_BYTES, &mapB,  p * 128, n0,    fb);
                    TMA_LOAD_2D(sa + SFA_OFF, &mapSA, m0,      p * 4, fb);
                    TMA_LOAD_2D(sa + SFB_OFF, &mapSB, n0,      p * 4, fb);
                }
            } else if (wid >= 4) {
                #pragma unroll
                for (int p = 0; p < NSTAGE; p++) {
                    const uint32_t sa = base + (uint32_t)p * STAGE_BYTES;
                    MBARRIER_WAIT_PARITY(full0 + (uint32_t)p * 8u, 0u);
                    sf_fill_smem(tmem, p, sa, lid, warp_off);
                    TCGEN05_FENCE_BEFORE();
                    if (lid == 0) MBARRIER_ARRIVE(sf_full0 + (uint32_t)p * 8u);
                }
            }
            first = false;
        }

        for (int c = 0; c < NCHUNK; c++, gc++) {
            const int s = (int)(gc & 3u);
            const uint32_t par = (gc >> 2) & 1u;
            const uint32_t sa = base + (uint32_t)s * STAGE_BYTES;

            if (wid == 0) {
                if (elect_one_pred()) {
                    // sf_full implies full (SF warps acquire full before arriving)
                    MBARRIER_WAIT_PARITY(sf_full0 + (uint32_t)s * 8u, par);
                    TCGEN05_FENCE_AFTER();
                    const uint64_t ad  = make_desc(sa);
                    const uint64_t bd0 = make_desc(sa + 16384u);
                    const uint64_t bd1 = make_desc(sa + 32768u);
                    const uint32_t sfbase = tmem + TMEM_SF + (uint32_t)s * SF_COLS;
                    #pragma unroll
                    for (int ks = 0; ks < 4; ks++) {
                        const uint32_t acc = (c > 0 || ks > 0) ? 1u : 0u;
                        const uint64_t ka = (uint64_t)(ks * 2);
                        const uint32_t sfa  = sfbase + (uint32_t)(ks * 4);
                        const uint32_t sfb0 = sfbase + 16u + (uint32_t)(ks * 8);
                        mma_nvf4_ss(tmem + 0u,   ad + ka, bd0 + ka, GEMM_IDESC, sfa, sfb0,      acc);
                        mma_nvf4_ss(tmem + 128u, ad + ka, bd1 + ka, GEMM_IDESC, sfa, sfb0 + 4u, acc);
                    }
                    TCGEN05_COMMIT(empty0 + (uint32_t)s * 8u);
                }
            } else if (wid == 1) {
                if (elect_one_pred()) {
                    int cc = c + NSTAGE, kx, ya, yb;
                    bool valid;
                    if (cc < NCHUNK)      { valid = true;  kx = cc;          ya = m0;  yb = n0;  }
                    else if (tn < NTILES) { valid = true;  kx = cc - NCHUNK; ya = m0n; yb = n0n; }
                    else                  { valid = false; kx = 0; ya = 0; yb = 0; }
                    if (valid) {
                        MBARRIER_WAIT_PARITY(empty0 + (uint32_t)s * 8u, par);
                        MBARRIER_EXPECT_TX(full0 + (uint32_t)s * 8u, STAGE_TX);
                        TMA_LOAD_2D(sa,           &mapA,  kx * 128, ya,     full0 + (uint32_t)s * 8u);
                        TMA_LOAD_2D(sa + A_BYTES, &mapB,  kx * 128, yb,     full0 + (uint32_t)s * 8u);
                        TMA_LOAD_2D(sa + SFA_OFF, &mapSA, ya,       kx * 4, full0 + (uint32_t)s * 8u);
                        TMA_LOAD_2D(sa + SFB_OFF, &mapSB, yb,       kx * 4, full0 + (uint32_t)s * 8u);
                    }
                }
            } else if (wid >= 4) {
                int cc = c + NSTAGE;
                bool valid = (cc < NCHUNK) || (tn < NTILES);
                if (valid) {
                    MBARRIER_WAIT_PARITY(empty0 + (uint32_t)s * 8u, par);        // TMEM free
                    MBARRIER_WAIT_PARITY(full0  + (uint32_t)s * 8u, par ^ 1u);   // SF slab arrived
                    sf_fill_smem(tmem, s, sa, lid, warp_off);
                    TCGEN05_FENCE_BEFORE();
                    if (lid == 0) MBARRIER_ARRIVE(sf_full0 + (uint32_t)s * 8u);
                }
            }
        }

        // Tile-done: one commit after all chunks (in-order MMA). Alias-safe per R5.
        if (wid == 0 && elect_one_pred()) TCGEN05_COMMIT(doneb);
        MBARRIER_WAIT_PARITY(doneb, tile_cnt & 1u);
        tile_cnt++;
        TCGEN05_FENCE_AFTER();

        // Epilogue: warp w -> rows m0+(w&3)*32+lid, cols (w>>2)*128..+127.
        {
            const int m = m0 + (wid & 3) * 32 + lid;
            const int nb = n0 + (wid >> 2) * 128;
            const uint32_t dbase = tmem + (uint32_t)((wid >> 2) * 128);
            float* orow = out + (size_t)m * N_DIM + nb;
            for (int cc = 0; cc < 128; cc += 32) {
                uint32_t d[32];
                TCGEN05_LD_32X32B_X32(d, dbase + (uint32_t)cc);
                TCGEN05_WAIT_LD();
                const float4* b4 = reinterpret_cast<const float4*>(bias + nb + cc);
                float4* o4 = reinterpret_cast<float4*>(orow + cc);
                #pragma unroll
                for (int q = 0; q < 8; q++) {
                    float4 bv = __ldg(b4 + q);
                    float4 ov;
                    ov.x = __uint_as_float(d[q * 4 + 0]) + bv.x;
                    ov.y = __uint_as_float(d[q * 4 + 1]) + bv.y;
                    ov.z = __uint_as_float(d[q * 4 + 2]) + bv.z;
                    ov.w = __uint_as_float(d[q * 4 + 3]) + bv.w;
                    o4[q] = ov;
                }
            }
            TCGEN05_FENCE_BEFORE();
        }

        t = tn;
    }

    __syncthreads();
    if (wid == 0) {
        TCGEN05_RELINQUISH();
        TCGEN05_DEALLOC(tmem, 512);
    }

#else
    // ------- baseline-pass fallback: correct SIMT decode GEMM (never selected) -------
    const int tt = blockIdx.x;
    const int m0 = (tt / NT_X) * BM;
    const int n0 = (tt % NT_X) * BN;
    for (int idx = tid; idx < BM * BN; idx += GEMM_THREADS) {
        const int m = m0 + idx / BN;
        const int n = n0 + idx % BN;
        float acc = 0.0f;
        for (int G = 0; G < GPR; G++) {
            uint64_t av = g_xq4[(size_t)m * GPR + G];
            uint64_t bv = g_wq4[(size_t)n * GPR + G];
            __nv_fp8_e4m3 sa8, sb8;
            sa8.__x = (uint8_t)(g_sfa[(size_t)(G >> 2) * M_DIM + m] >> ((G & 3) * 8));
            sb8.__x = (uint8_t)(g_sfb[(size_t)(G >> 2) * N_DIM + n] >> ((G & 3) * 8));
            float fs = float(sa8) * float(sb8);
            float sum = 0.0f;
            #pragma unroll
            for (int i = 0; i < 16; i++) {
                uint32_t ca = (uint32_t)(av >> (4 * i)) & 15u;
                uint32_t cb = (uint32_t)(bv >> (4 * i)) & 15u;
                float va = c_lut[ca & 7u]; if (ca & 8u) va = -va;
                float vb = c_lut[cb & 7u]; if (cb & 8u) vb = -vb;
                sum += va * vb;
            }
            acc += sum * fs;
        }
        out[(size_t)m * N_DIM + n] = acc + __ldg(bias + n);
    }
#endif
}

// ---------------- host: tensormap encode ----------------
typedef CUresult (*PFN_encodeTiled)(
    CUtensorMap*, CUtensorMapDataType, cuuint32_t, void*,
    const cuuint64_t*, const cuuint64_t*, const cuuint32_t*, const cuuint32_t*,
    CUtensorMapInterleave, CUtensorMapSwizzle, CUtensorMapL2promotion,
    CUtensorMapFloatOOBfill);

static PFN_encodeTiled get_encoder() {
    void* p = nullptr;
    cudaDriverEntryPointQueryResult st;
    cudaGetDriverEntryPointByVersion("cuTensorMapEncodeTiled", &p, 12000,
                                     cudaEnableDefault, &st);
    return (PFN_encodeTiled)p;
}

static void encode_map_u8(CUtensorMap* map, void* ptr, uint64_t rows,
                          uint64_t row_bytes, uint32_t box_rows) {
    cuuint64_t dims[2]    = {row_bytes, rows};
    cuuint64_t strides[1] = {row_bytes};
    cuuint32_t box[2]     = {128, box_rows};
    cuuint32_t estr[2]    = {1, 1};
    get_encoder()(map, CU_TENSOR_MAP_DATA_TYPE_UINT8, 2, ptr,
       dims, strides, box, estr,
       CU_TENSOR_MAP_INTERLEAVE_NONE, CU_TENSOR_MAP_SWIZZLE_128B,
       CU_TENSOR_MAP_L2_PROMOTION_L2_128B,
       CU_TENSOR_MAP_FLOAT_OOB_FILL_NONE);
}

static void encode_map_sf(CUtensorMap* map, void* ptr, uint64_t cols, uint32_t box_cols) {
    cuuint64_t dims[2]    = {cols, GWR};         // u32 elements per row, GWR rows
    cuuint64_t strides[1] = {cols * 4};
    cuuint32_t box[2]     = {box_cols, 4};
    cuuint32_t estr[2]    = {1, 1};
    get_encoder()(map, CU_TENSOR_MAP_DATA_TYPE_UINT32, 2, ptr,
       dims, strides, box, estr,
       CU_TENSOR_MAP_INTERLEAVE_NONE, CU_TENSOR_MAP_SWIZZLE_NONE,
       CU_TENSOR_MAP_L2_PROMOTION_L2_128B,
       CU_TENSOR_MAP_FLOAT_OOB_FILL_NONE);
}

// ---------------- launcher ----------------
extern "C" void kernel_launch(void* const* d_in, const int* in_sizes, int n_in,
                              void* d_out, int out_size) {
    (void)in_sizes; (void)n_in; (void)out_size;
    const float* x    = (const float*)d_in[0];
    const float* w    = (const float*)d_in[1];
    const float* bias = (const float*)d_in[2];
    float* out = (float*)d_out;

    uint64_t *xq4 = nullptr, *wq4 = nullptr;
    uint32_t *sfa = nullptr, *sfb = nullptr;
    cudaGetSymbolAddress((void**)&xq4, g_xq4);
    cudaGetSymbolAddress((void**)&wq4, g_wq4);
    cudaGetSymbolAddress((void**)&sfa, g_sfa);
    cudaGetSymbolAddress((void**)&sfb, g_sfb);

    CUtensorMap mapA, mapB, mapSA, mapSB;
    encode_map_u8(&mapA, xq4, M_DIM, K_DIM / 2, 128);
    encode_map_u8(&mapB, wq4, N_DIM, K_DIM / 2, 256);
    encode_map_sf(&mapSA, sfa, M_DIM, 128);
    encode_map_sf(&mapSB, sfb, N_DIM, 256);

    const int xg = M_DIM * GPR;
    const int wg = N_DIM * GPR;
    quant_fp4_kernel<<<xg / 256, 256>>>(x, xq4, (uint8_t*)sfa, M_DIM, xg);
    quant_fp4_kernel<<<wg / 256, 256>>>(w, wq4, (uint8_t*)sfb, N_DIM, wg);

    reset_ctr_kernel<<<1, 1>>>();

    cudaFuncSetAttribute(gemm_fp4, cudaFuncAttributeMaxDynamicSharedMemorySize, GEMM_SMEM_BYTES);
    gemm_fp4<<<NTILES, GEMM_THREADS, GEMM_SMEM_BYTES>>>(mapA, mapB, mapSA, mapSB, bias, out);
}